// round 1
// baseline (speedup 1.0000x reference)
#include <cuda_runtime.h>
#include <math.h>

#define HW   256
#define PIX  65536
#define NB   8
#define NC   64
#define P    65   // smem pitch for 64-wide tiles (conflict-free)

// ---- scratch (allocation-free: device globals) ----
__device__ float g_gap[NB * NC];
__device__ float g_gate[NB * NC];
__device__ float g_A[(size_t)NB * PIX * NC];   // gated attn out, NHWC
__device__ float g_x1[(size_t)NB * PIX * NC];  // x + attn + ms, NHWC

// ============================================================
// K1: global average pool per (b,c)
// ============================================================
__global__ void k_gap(const float* __restrict__ x) {
    int bc = blockIdx.x;              // 0..511
    const float* p = x + (size_t)bc * PIX;
    float s = 0.f;
    for (int i = threadIdx.x; i < PIX; i += 256) s += p[i];
    __shared__ float red[256];
    red[threadIdx.x] = s;
    __syncthreads();
    for (int st = 128; st > 0; st >>= 1) {
        if (threadIdx.x < st) red[threadIdx.x] += red[threadIdx.x + st];
        __syncthreads();
    }
    if (threadIdx.x == 0) g_gap[bc] = red[0] * (1.f / PIX);
}

// ============================================================
// K2: SE gate (tiny MLP), one block of 512 threads
// ============================================================
__global__ void k_gate(const float* __restrict__ se1_w, const float* __restrict__ se1_b,
                       const float* __restrict__ se2_w, const float* __restrict__ se2_b) {
    __shared__ float se[NB][4];
    int tid = threadIdx.x;
    if (tid < 32) {
        int b = tid >> 2, j = tid & 3;
        float s = se1_b[j];
        for (int c = 0; c < NC; c++) s += g_gap[b * NC + c] * se1_w[j * NC + c];
        se[b][j] = fmaxf(s, 0.f);
    }
    __syncthreads();
    int b = tid >> 6, o = tid & 63;
    float s = se2_b[o];
    #pragma unroll
    for (int j = 0; j < 4; j++) s += se[b][j] * se2_w[o * 4 + j];
    g_gate[tid] = 1.f / (1.f + __expf(-s));
}

// ============================================================
// 64x64x64 smem matmuls with 4x4 register tiles (256 threads)
// C[t][o] = scale * (bias[o] + sum_c A[t][c]*B[o][c])
// ============================================================
__device__ __forceinline__ void mm_tn(const float* __restrict__ Am, const float* __restrict__ Bm,
                                      float* __restrict__ Cm, const float* __restrict__ bias,
                                      float scale) {
    int tid = threadIdx.x;
    int tb = (tid >> 4) << 2, ob = (tid & 15) << 2;
    float acc[4][4];
    #pragma unroll
    for (int i = 0; i < 4; i++)
        #pragma unroll
        for (int j = 0; j < 4; j++) acc[i][j] = bias ? bias[ob + j] : 0.f;
    #pragma unroll 8
    for (int c = 0; c < NC; c++) {
        float a0 = Am[(tb + 0) * P + c], a1 = Am[(tb + 1) * P + c];
        float a2 = Am[(tb + 2) * P + c], a3 = Am[(tb + 3) * P + c];
        float b0 = Bm[(ob + 0) * P + c], b1 = Bm[(ob + 1) * P + c];
        float b2 = Bm[(ob + 2) * P + c], b3 = Bm[(ob + 3) * P + c];
        acc[0][0] += a0 * b0; acc[0][1] += a0 * b1; acc[0][2] += a0 * b2; acc[0][3] += a0 * b3;
        acc[1][0] += a1 * b0; acc[1][1] += a1 * b1; acc[1][2] += a1 * b2; acc[1][3] += a1 * b3;
        acc[2][0] += a2 * b0; acc[2][1] += a2 * b1; acc[2][2] += a2 * b2; acc[2][3] += a2 * b3;
        acc[3][0] += a3 * b0; acc[3][1] += a3 * b1; acc[3][2] += a3 * b2; acc[3][3] += a3 * b3;
    }
    #pragma unroll
    for (int i = 0; i < 4; i++)
        #pragma unroll
        for (int j = 0; j < 4; j++) Cm[(tb + i) * P + ob + j] = acc[i][j] * scale;
}

// C[t][c] = sum_u A[t][u] * B[u][c]
__device__ __forceinline__ void mm_nn(const float* __restrict__ Am, const float* __restrict__ Bm,
                                      float* __restrict__ Cm) {
    int tid = threadIdx.x;
    int tb = (tid >> 4) << 2, ob = (tid & 15) << 2;
    float acc[4][4];
    #pragma unroll
    for (int i = 0; i < 4; i++)
        #pragma unroll
        for (int j = 0; j < 4; j++) acc[i][j] = 0.f;
    #pragma unroll 8
    for (int u = 0; u < NC; u++) {
        float a0 = Am[(tb + 0) * P + u], a1 = Am[(tb + 1) * P + u];
        float a2 = Am[(tb + 2) * P + u], a3 = Am[(tb + 3) * P + u];
        float b0 = Bm[u * P + ob + 0], b1 = Bm[u * P + ob + 1];
        float b2 = Bm[u * P + ob + 2], b3 = Bm[u * P + ob + 3];
        acc[0][0] += a0 * b0; acc[0][1] += a0 * b1; acc[0][2] += a0 * b2; acc[0][3] += a0 * b3;
        acc[1][0] += a1 * b0; acc[1][1] += a1 * b1; acc[1][2] += a1 * b2; acc[1][3] += a1 * b3;
        acc[2][0] += a2 * b0; acc[2][1] += a2 * b1; acc[2][2] += a2 * b2; acc[2][3] += a2 * b3;
        acc[3][0] += a3 * b0; acc[3][1] += a3 * b1; acc[3][2] += a3 * b2; acc[3][3] += a3 * b3;
    }
    #pragma unroll
    for (int i = 0; i < 4; i++)
        #pragma unroll
        for (int j = 0; j < 4; j++) Cm[(tb + i) * P + ob + j] = acc[i][j];
}

// ============================================================
// K3: fused window attention (one CTA per 8x8 window)
// q/k/v proj -> softmax(QK^T/8) -> @V -> out proj -> * gate -> A (NHWC)
// ============================================================
__global__ void k_attn(const float* __restrict__ x,
                       const float* __restrict__ qk_w, const float* __restrict__ qk_b,
                       const float* __restrict__ v_w,  const float* __restrict__ v_b,
                       const float* __restrict__ out_w, const float* __restrict__ out_b) {
    extern __shared__ float sm[];
    float* xs = sm;             // [64][P]
    float* qs = sm + 4160;
    float* ks = sm + 8320;
    float* vs = sm + 12480;
    float* ss = sm + 16640;
    float* ws = sm + 20800;     // weight buffer [64][P]
    int tid = threadIdx.x;
    int wid = blockIdx.x;
    int b = wid >> 10;
    int nh = (wid >> 5) & 31;
    int nw = wid & 31;
    int h0 = nh * 8, w0 = nw * 8;
    const float* xb = x + (size_t)b * NC * PIX;

    // load window tokens (c-major loop -> coalesced-ish 32B runs)
    for (int idx = tid; idx < 4096; idx += 256) {
        int c = idx >> 6, t = idx & 63;
        int hh = t >> 3, wwi = t & 7;
        xs[t * P + c] = xb[(size_t)c * PIX + (h0 + hh) * HW + (w0 + wwi)];
    }
    for (int idx = tid; idx < 4096; idx += 256) ws[(idx >> 6) * P + (idx & 63)] = qk_w[idx];
    __syncthreads();
    mm_tn(xs, ws, qs, qk_b, 1.f);            // Q
    __syncthreads();
    for (int idx = tid; idx < 4096; idx += 256) ws[(idx >> 6) * P + (idx & 63)] = qk_w[4096 + idx];
    __syncthreads();
    mm_tn(xs, ws, ks, qk_b + 64, 1.f);       // K
    __syncthreads();
    for (int idx = tid; idx < 4096; idx += 256) ws[(idx >> 6) * P + (idx & 63)] = v_w[idx];
    __syncthreads();
    mm_tn(xs, ws, vs, v_b, 1.f);             // V
    __syncthreads();
    mm_tn(qs, ks, ss, (const float*)0, 0.125f);  // scores = QK^T * SCALE
    __syncthreads();
    if (tid < 64) {                          // softmax row
        float m = -1e30f;
        for (int u = 0; u < 64; u++) m = fmaxf(m, ss[tid * P + u]);
        float s = 0.f;
        for (int u = 0; u < 64; u++) { float e = __expf(ss[tid * P + u] - m); ss[tid * P + u] = e; s += e; }
        float inv = 1.f / s;
        for (int u = 0; u < 64; u++) ss[tid * P + u] *= inv;
    }
    __syncthreads();
    // ow = attn @ V (into xs, which is dead now) + load out_w in parallel
    mm_nn(ss, vs, xs);
    for (int idx = tid; idx < 4096; idx += 256) ws[(idx >> 6) * P + (idx & 63)] = out_w[idx];
    __syncthreads();
    // out proj + gate, write NHWC
    {
        int tb = (tid >> 4) << 2, ob = (tid & 15) << 2;
        float acc[4][4];
        #pragma unroll
        for (int i = 0; i < 4; i++)
            #pragma unroll
            for (int j = 0; j < 4; j++) acc[i][j] = out_b[ob + j];
        #pragma unroll 8
        for (int c = 0; c < NC; c++) {
            float a0 = xs[(tb + 0) * P + c], a1 = xs[(tb + 1) * P + c];
            float a2 = xs[(tb + 2) * P + c], a3 = xs[(tb + 3) * P + c];
            float b0 = ws[(ob + 0) * P + c], b1 = ws[(ob + 1) * P + c];
            float b2 = ws[(ob + 2) * P + c], b3 = ws[(ob + 3) * P + c];
            acc[0][0] += a0 * b0; acc[0][1] += a0 * b1; acc[0][2] += a0 * b2; acc[0][3] += a0 * b3;
            acc[1][0] += a1 * b0; acc[1][1] += a1 * b1; acc[1][2] += a1 * b2; acc[1][3] += a1 * b3;
            acc[2][0] += a2 * b0; acc[2][1] += a2 * b1; acc[2][2] += a2 * b2; acc[2][3] += a2 * b3;
            acc[3][0] += a3 * b0; acc[3][1] += a3 * b1; acc[3][2] += a3 * b2; acc[3][3] += a3 * b3;
        }
        #pragma unroll
        for (int i = 0; i < 4; i++) {
            int t = tb + i;
            int hh = t >> 3, wwi = t & 7;
            size_t gp = ((size_t)(b * HW + h0 + hh) * HW + (w0 + wwi)) * (size_t)NC;
            #pragma unroll
            for (int j = 0; j < 4; j++) {
                int o = ob + j;
                g_A[gp + o] = acc[i][j] * g_gate[b * NC + o];
            }
        }
    }
}

// ============================================================
// K4: 3x3 conv 64->32 (+relu) -> 1x1 32->64, + x + A -> x1 (NHWC)
// One CTA per (b, 16x16 tile); channel-chunked halo in smem.
// ============================================================
__global__ void k_ms(const float* __restrict__ x,
                     const float* __restrict__ ms1_w, const float* __restrict__ ms1_b,
                     const float* __restrict__ ms2_w, const float* __restrict__ ms2_b) {
    extern __shared__ float sm[];
    float* xh    = sm;                   // 16 ch * 18*18 halo = 5184
    float* w1s   = sm + 5184;            // [(i*9+k)*32 + o]   = 4608
    float* stage = sm + 5184 + 4608;     // [256][P]           = 16640
    float* w2s   = sm + 5184 + 4608 + 16640;  // [64][32]      = 2048
    int tid = threadIdx.x;
    int b = blockIdx.z;
    int gy0 = blockIdx.y << 4, gx0 = blockIdx.x << 4;
    int py = tid >> 4, px = tid & 15;

    // ms2 weights once
    for (int idx = tid; idx < 2048; idx += 256) w2s[idx] = ms2_w[idx];

    float acc[32];
    #pragma unroll
    for (int o = 0; o < 32; o++) acc[o] = 0.f;

    for (int ch = 0; ch < 4; ch++) {
        int ic0 = ch << 4;
        __syncthreads();  // protect xh/w1s from previous-iteration readers
        for (int idx = tid; idx < 16 * 324; idx += 256) {
            int i = idx / 324, r = idx - i * 324;
            int hy = r / 18, hx = r - hy * 18;
            int gy = gy0 + hy - 1, gx = gx0 + hx - 1;
            float v = 0.f;
            if (gy >= 0 && gy < HW && gx >= 0 && gx < HW)
                v = x[((size_t)(b * NC + ic0 + i)) * PIX + gy * HW + gx];
            xh[idx] = v;
        }
        for (int idx = tid; idx < 4608; idx += 256) {
            int i = idx / 288, r = idx - i * 288;
            int k = r >> 5, o = r & 31;
            w1s[idx] = ms1_w[(size_t)(o * NC + ic0 + i) * 9 + k];
        }
        __syncthreads();
        #pragma unroll
        for (int i = 0; i < 16; i++) {
            #pragma unroll
            for (int k = 0; k < 9; k++) {
                int ky = k / 3, kx = k - ky * 3;
                float xv = xh[i * 324 + (py + ky) * 18 + (px + kx)];
                const float4* w4 = (const float4*)&w1s[(i * 9 + k) * 32];
                #pragma unroll
                for (int j = 0; j < 8; j++) {
                    float4 w = w4[j];
                    acc[4 * j + 0] += xv * w.x;
                    acc[4 * j + 1] += xv * w.y;
                    acc[4 * j + 2] += xv * w.z;
                    acc[4 * j + 3] += xv * w.w;
                }
            }
        }
    }
    // relu(conv + b1)
    #pragma unroll
    for (int o = 0; o < 32; o++) acc[o] = fmaxf(acc[o] + __ldg(&ms1_b[o]), 0.f);
    // 1x1 32->64
    for (int o2 = 0; o2 < 64; o2++) {
        float s = __ldg(&ms2_b[o2]);
        const float4* w4 = (const float4*)&w2s[o2 * 32];
        #pragma unroll
        for (int q = 0; q < 8; q++) {
            float4 w = w4[q];
            s += acc[4 * q + 0] * w.x + acc[4 * q + 1] * w.y
               + acc[4 * q + 2] * w.z + acc[4 * q + 3] * w.w;
        }
        stage[tid * P + o2] = s;
    }
    // + x residual (NCHW reads, per-channel coalesced)
    for (int c = 0; c < NC; c++) {
        float xv = x[((size_t)(b * NC + c)) * PIX + (gy0 + py) * HW + (gx0 + px)];
        stage[tid * P + c] += xv;
    }
    __syncthreads();
    // + attention residual, write x1 NHWC coalesced
    for (int idx = tid; idx < 16384; idx += 256) {
        int p = idx >> 6, c = idx & 63;
        int gy = gy0 + (p >> 4), gx = gx0 + (p & 15);
        size_t g = ((size_t)(b * HW + gy) * HW + gx) * (size_t)NC + c;
        g_x1[g] = stage[p * P + c] + g_A[g];
    }
}

// ============================================================
// K5: LN + fc1 + GELU(tanh) + fc2 + residual; NHWC->NCHW write
// One CTA per 64 consecutive pixels.
// ============================================================
__device__ __forceinline__ float gelu_tanh(float v) {
    float u = 0.7978845608028654f * (v + 0.044715f * v * v * v);
    return 0.5f * v * (1.f + tanhf(u));
}

__global__ void k_ffn(const float* __restrict__ ln_g, const float* __restrict__ ln_b,
                      const float* __restrict__ fc1_w, const float* __restrict__ fc1_b,
                      const float* __restrict__ fc2_w, const float* __restrict__ fc2_b,
                      float* __restrict__ out) {
    extern __shared__ float sm[];
    float* t  = sm;          // x1 tile [64][P]
    float* tn = sm + 4160;
    float* h  = sm + 8320;
    float* ws = sm + 12480;
    int tid = threadIdx.x;
    int blk = blockIdx.x;
    int b = blk >> 10;
    int rem = blk & 1023;
    int hh = rem >> 2;
    int w0 = (rem & 3) << 6;
    size_t base = ((size_t)(b * HW + hh) * HW + w0) * (size_t)NC;

    for (int idx = tid; idx < 4096; idx += 256)
        t[(idx >> 6) * P + (idx & 63)] = g_x1[base + idx];
    for (int idx = tid; idx < 4096; idx += 256)
        ws[(idx >> 6) * P + (idx & 63)] = fc1_w[idx];
    __syncthreads();
    if (tid < 64) {
        float mu = 0.f;
        for (int c = 0; c < NC; c++) mu += t[tid * P + c];
        mu *= (1.f / NC);
        float var = 0.f;
        for (int c = 0; c < NC; c++) { float d = t[tid * P + c] - mu; var += d * d; }
        var *= (1.f / NC);
        float rs = rsqrtf(var + 1e-5f);
        for (int c = 0; c < NC; c++)
            tn[tid * P + c] = (t[tid * P + c] - mu) * rs * __ldg(&ln_g[c]) + __ldg(&ln_b[c]);
    }
    __syncthreads();
    // h = gelu(tn @ fc1^T + b1)
    {
        int tb = (tid >> 4) << 2, ob = (tid & 15) << 2;
        float acc[4][4];
        #pragma unroll
        for (int i = 0; i < 4; i++)
            #pragma unroll
            for (int j = 0; j < 4; j++) acc[i][j] = fc1_b[ob + j];
        #pragma unroll 8
        for (int c = 0; c < NC; c++) {
            float a0 = tn[(tb + 0) * P + c], a1 = tn[(tb + 1) * P + c];
            float a2 = tn[(tb + 2) * P + c], a3 = tn[(tb + 3) * P + c];
            float b0 = ws[(ob + 0) * P + c], b1 = ws[(ob + 1) * P + c];
            float b2 = ws[(ob + 2) * P + c], b3 = ws[(ob + 3) * P + c];
            acc[0][0] += a0 * b0; acc[0][1] += a0 * b1; acc[0][2] += a0 * b2; acc[0][3] += a0 * b3;
            acc[1][0] += a1 * b0; acc[1][1] += a1 * b1; acc[1][2] += a1 * b2; acc[1][3] += a1 * b3;
            acc[2][0] += a2 * b0; acc[2][1] += a2 * b1; acc[2][2] += a2 * b2; acc[2][3] += a2 * b3;
            acc[3][0] += a3 * b0; acc[3][1] += a3 * b1; acc[3][2] += a3 * b2; acc[3][3] += a3 * b3;
        }
        #pragma unroll
        for (int i = 0; i < 4; i++)
            #pragma unroll
            for (int j = 0; j < 4; j++)
                h[(tb + i) * P + ob + j] = gelu_tanh(acc[i][j]);
    }
    __syncthreads();
    for (int idx = tid; idx < 4096; idx += 256)
        ws[(idx >> 6) * P + (idx & 63)] = fc2_w[idx];
    __syncthreads();
    // out = x1 + h @ fc2^T + b2 ; NCHW write (o-major tile -> coalesced)
    {
        int ob = (tid >> 4) << 2, pb = (tid & 15) << 2;
        float acc[4][4];  // [o][p]
        #pragma unroll
        for (int j = 0; j < 4; j++)
            #pragma unroll
            for (int i = 0; i < 4; i++) acc[j][i] = fc2_b[ob + j];
        #pragma unroll 8
        for (int c = 0; c < NC; c++) {
            float a0 = h[(pb + 0) * P + c], a1 = h[(pb + 1) * P + c];
            float a2 = h[(pb + 2) * P + c], a3 = h[(pb + 3) * P + c];
            float b0 = ws[(ob + 0) * P + c], b1 = ws[(ob + 1) * P + c];
            float b2 = ws[(ob + 2) * P + c], b3 = ws[(ob + 3) * P + c];
            acc[0][0] += b0 * a0; acc[0][1] += b0 * a1; acc[0][2] += b0 * a2; acc[0][3] += b0 * a3;
            acc[1][0] += b1 * a0; acc[1][1] += b1 * a1; acc[1][2] += b1 * a2; acc[1][3] += b1 * a3;
            acc[2][0] += b2 * a0; acc[2][1] += b2 * a1; acc[2][2] += b2 * a2; acc[2][3] += b2 * a3;
            acc[3][0] += b3 * a0; acc[3][1] += b3 * a1; acc[3][2] += b3 * a2; acc[3][3] += b3 * a3;
        }
        #pragma unroll
        for (int j = 0; j < 4; j++) {
            int o = ob + j;
            size_t gbase = ((size_t)(b * NC + o)) * PIX + (size_t)hh * HW + w0;
            #pragma unroll
            for (int i = 0; i < 4; i++) {
                int p = pb + i;
                out[gbase + p] = t[p * P + o] + acc[j][i];
            }
        }
    }
}

// ============================================================
extern "C" void kernel_launch(void* const* d_in, const int* in_sizes, int n_in,
                              void* d_out, int out_size) {
    const float* x     = (const float*)d_in[0];
    const float* qk_w  = (const float*)d_in[1];
    const float* qk_b  = (const float*)d_in[2];
    const float* v_w   = (const float*)d_in[3];
    const float* v_b   = (const float*)d_in[4];
    const float* out_w = (const float*)d_in[5];
    const float* out_b = (const float*)d_in[6];
    const float* ms1_w = (const float*)d_in[7];
    const float* ms1_b = (const float*)d_in[8];
    const float* ms2_w = (const float*)d_in[9];
    const float* ms2_b = (const float*)d_in[10];
    const float* se1_w = (const float*)d_in[11];
    const float* se1_b = (const float*)d_in[12];
    const float* se2_w = (const float*)d_in[13];
    const float* se2_b = (const float*)d_in[14];
    const float* ln_g  = (const float*)d_in[15];
    const float* ln_b  = (const float*)d_in[16];
    const float* fc1_w = (const float*)d_in[17];
    const float* fc1_b = (const float*)d_in[18];
    const float* fc2_w = (const float*)d_in[19];
    const float* fc2_b = (const float*)d_in[20];
    float* out = (float*)d_out;

    const int smem_attn = 6 * 64 * P * 4;      // 99840
    const int smem_ms   = (5184 + 4608 + 16640 + 2048) * 4;  // 113920
    const int smem_ffn  = 4 * 64 * P * 4;      // 66560
    cudaFuncSetAttribute(k_attn, cudaFuncAttributeMaxDynamicSharedMemorySize, smem_attn);
    cudaFuncSetAttribute(k_ms,   cudaFuncAttributeMaxDynamicSharedMemorySize, smem_ms);
    cudaFuncSetAttribute(k_ffn,  cudaFuncAttributeMaxDynamicSharedMemorySize, smem_ffn);

    k_gap<<<NB * NC, 256>>>(x);
    k_gate<<<1, 512>>>(se1_w, se1_b, se2_w, se2_b);
    k_attn<<<8192, 256, smem_attn>>>(x, qk_w, qk_b, v_w, v_b, out_w, out_b);
    k_ms<<<dim3(16, 16, NB), 256, smem_ms>>>(x, ms1_w, ms1_b, ms2_w, ms2_b);
    k_ffn<<<8192, 256, smem_ffn>>>(ln_g, ln_b, fc1_w, fc1_b, fc2_w, fc2_b, out);
}

// round 3
// speedup vs baseline: 1.5726x; 1.5726x over previous
#include <cuda_runtime.h>
#include <cuda_bf16.h>
#include <cstdint>
#include <stdint.h>
#include <math.h>

#define HW   256
#define PIX  65536
#define NB   8
#define NC   64
#define BP   72    // bf16 smem pitch (conflict-free for mma frag loads)
#define FP   65    // fp32 smem pitch for row-parallel ops

// ---- scratch (allocation-free: device globals) ----
__device__ float g_gap[NB * NC];
__device__ float g_gate[NB * NC];
__device__ float g_A[(size_t)NB * PIX * NC];   // gated attn out, NHWC
__device__ float g_x1[(size_t)NB * PIX * NC];  // x + attn + ms, NHWC

// ============================================================
// warp-level 64xK GEMM slab on tensor cores:
// C[64x64] = A[64x64] * B^T, A row-major [m][k] (pitch BP bf16),
// B row-major [n][k] (pitch BP bf16)  -> mma row.col form.
// Warp computes rows r0..r0+15, cols c0..c0+31 into acc[4][4].
// ============================================================
__device__ __forceinline__ void gemm64(const __nv_bfloat16* __restrict__ As,
                                       const __nv_bfloat16* __restrict__ Bs,
                                       int r0, int c0, int lane, float acc[4][4]) {
    int g = lane >> 2, tg = lane & 3;
    const __nv_bfloat16* arow = As + (r0 + g) * BP + 2 * tg;
    #pragma unroll
    for (int kt = 0; kt < 4; kt++) {
        uint32_t a0 = *(const uint32_t*)(arow + kt * 16);
        uint32_t a1 = *(const uint32_t*)(arow + 8 * BP + kt * 16);
        uint32_t a2 = *(const uint32_t*)(arow + kt * 16 + 8);
        uint32_t a3 = *(const uint32_t*)(arow + 8 * BP + kt * 16 + 8);
        #pragma unroll
        for (int nt = 0; nt < 4; nt++) {
            const __nv_bfloat16* brow = Bs + (c0 + nt * 8 + g) * BP + 2 * tg + kt * 16;
            uint32_t b0 = *(const uint32_t*)(brow);
            uint32_t b1 = *(const uint32_t*)(brow + 8);
            asm volatile(
                "mma.sync.aligned.m16n8k16.row.col.f32.bf16.bf16.f32 "
                "{%0,%1,%2,%3},{%4,%5,%6,%7},{%8,%9},{%0,%1,%2,%3};"
                : "+f"(acc[nt][0]), "+f"(acc[nt][1]), "+f"(acc[nt][2]), "+f"(acc[nt][3])
                : "r"(a0), "r"(a1), "r"(a2), "r"(a3), "r"(b0), "r"(b1));
        }
    }
}

__device__ __forceinline__ void acc_bias(float acc[4][4], const float* __restrict__ bias,
                                         int c0, int lane) {
    int tg = lane & 3;
    #pragma unroll
    for (int nt = 0; nt < 4; nt++) {
        float b0 = __ldg(bias + c0 + nt * 8 + 2 * tg);
        float b1 = __ldg(bias + c0 + nt * 8 + 2 * tg + 1);
        acc[nt][0] = b0; acc[nt][1] = b1; acc[nt][2] = b0; acc[nt][3] = b1;
    }
}

__device__ __forceinline__ void acc_zero(float acc[4][4]) {
    #pragma unroll
    for (int nt = 0; nt < 4; nt++)
        #pragma unroll
        for (int i = 0; i < 4; i++) acc[nt][i] = 0.f;
}

// store acc as bf16 row-major [row][col], pitch BP
__device__ __forceinline__ void store_bf16(__nv_bfloat16* __restrict__ D, float acc[4][4],
                                           int r0, int c0, int lane) {
    int g = lane >> 2, tg = lane & 3;
    #pragma unroll
    for (int nt = 0; nt < 4; nt++) {
        int col = c0 + nt * 8 + 2 * tg;
        __nv_bfloat162 p0 = __floats2bfloat162_rn(acc[nt][0], acc[nt][1]);
        __nv_bfloat162 p1 = __floats2bfloat162_rn(acc[nt][2], acc[nt][3]);
        *(__nv_bfloat162*)(D + (r0 + g) * BP + col) = p0;
        *(__nv_bfloat162*)(D + (r0 + g + 8) * BP + col) = p1;
    }
}

// ============================================================
// K1: global average pool per (b,c)
// ============================================================
__global__ void k_gap(const float* __restrict__ x) {
    int bc = blockIdx.x;
    const float* p = x + (size_t)bc * PIX;
    float s = 0.f;
    for (int i = threadIdx.x; i < PIX; i += 256) s += p[i];
    __shared__ float red[256];
    red[threadIdx.x] = s;
    __syncthreads();
    for (int st = 128; st > 0; st >>= 1) {
        if (threadIdx.x < st) red[threadIdx.x] += red[threadIdx.x + st];
        __syncthreads();
    }
    if (threadIdx.x == 0) g_gap[bc] = red[0] * (1.f / PIX);
}

// ============================================================
// K2: SE gate
// ============================================================
__global__ void k_gate(const float* __restrict__ se1_w, const float* __restrict__ se1_b,
                       const float* __restrict__ se2_w, const float* __restrict__ se2_b) {
    __shared__ float se[NB][4];
    int tid = threadIdx.x;
    if (tid < 32) {
        int b = tid >> 2, j = tid & 3;
        float s = se1_b[j];
        for (int c = 0; c < NC; c++) s += g_gap[b * NC + c] * se1_w[j * NC + c];
        se[b][j] = fmaxf(s, 0.f);
    }
    __syncthreads();
    int b = tid >> 6, o = tid & 63;
    float s = se2_b[o];
    #pragma unroll
    for (int j = 0; j < 4; j++) s += se[b][j] * se2_w[o * 4 + j];
    g_gate[tid] = 1.f / (1.f + __expf(-s));
}

// ============================================================
// K3: fused window attention, tensor-core bf16 GEMMs
// ============================================================
__global__ void __launch_bounds__(256) k_attn(
        const float* __restrict__ x,
        const float* __restrict__ qk_w, const float* __restrict__ qk_b,
        const float* __restrict__ v_w,  const float* __restrict__ v_b,
        const float* __restrict__ out_w, const float* __restrict__ out_b) {
    extern __shared__ __nv_bfloat16 smb[];
    __nv_bfloat16* xs = smb;              // [64][BP], later reused as ow
    __nv_bfloat16* wq = smb + 4608;
    __nv_bfloat16* wk = smb + 9216;
    __nv_bfloat16* wv = smb + 13824;
    __nv_bfloat16* wo = smb + 18432;
    __nv_bfloat16* qs = smb + 23040;
    __nv_bfloat16* ks = smb + 27648;
    __nv_bfloat16* vT = smb + 32256;      // transposed V: [c][s]
    __nv_bfloat16* ps = smb + 36864;      // softmax probs
    float*         ss = (float*)(smb + 41472);  // fp32 scores [64][BP]

    int tid = threadIdx.x;
    int lane = tid & 31, wid = tid >> 5;
    int r0 = (wid >> 1) * 16, c0 = (wid & 1) * 32;
    int blk = blockIdx.x;
    int b = blk >> 10;
    int nh = (blk >> 5) & 31, nw = blk & 31;
    int h0 = nh * 8, w0 = nw * 8;
    const float* xb = x + (size_t)b * NC * PIX;

    // load window tokens + weights (bf16)
    for (int idx = tid; idx < 4096; idx += 256) {
        int c = idx >> 6, t = idx & 63;
        xs[t * BP + c] = __float2bfloat16(xb[(size_t)c * PIX + (h0 + (t >> 3)) * HW + (w0 + (t & 7))]);
    }
    for (int idx = tid; idx < 4096; idx += 256) {
        int o = idx >> 6, c = idx & 63;
        wq[o * BP + c] = __float2bfloat16(qk_w[idx]);
        wk[o * BP + c] = __float2bfloat16(qk_w[4096 + idx]);
        wv[o * BP + c] = __float2bfloat16(v_w[idx]);
        wo[o * BP + c] = __float2bfloat16(out_w[idx]);
    }
    __syncthreads();

    float acc[4][4];
    // Q, K, V projections
    acc_bias(acc, qk_b, c0, lane);
    gemm64(xs, wq, r0, c0, lane, acc);
    store_bf16(qs, acc, r0, c0, lane);

    acc_bias(acc, qk_b + 64, c0, lane);
    gemm64(xs, wk, r0, c0, lane, acc);
    store_bf16(ks, acc, r0, c0, lane);

    acc_bias(acc, v_b, c0, lane);
    gemm64(xs, wv, r0, c0, lane, acc);
    {   // transposed store: vT[col][row]
        int g = lane >> 2, tg = lane & 3;
        #pragma unroll
        for (int nt = 0; nt < 4; nt++) {
            int col = c0 + nt * 8 + 2 * tg;
            vT[col * BP + r0 + g]           = __float2bfloat16(acc[nt][0]);
            vT[(col + 1) * BP + r0 + g]     = __float2bfloat16(acc[nt][1]);
            vT[col * BP + r0 + g + 8]       = __float2bfloat16(acc[nt][2]);
            vT[(col + 1) * BP + r0 + g + 8] = __float2bfloat16(acc[nt][3]);
        }
    }
    __syncthreads();

    // scores = Q K^T (fp32 to smem)
    acc_zero(acc);
    gemm64(qs, ks, r0, c0, lane, acc);
    {
        int g = lane >> 2, tg = lane & 3;
        #pragma unroll
        for (int nt = 0; nt < 4; nt++) {
            int col = c0 + nt * 8 + 2 * tg;
            ss[(r0 + g) * BP + col]     = acc[nt][0];
            ss[(r0 + g) * BP + col + 1] = acc[nt][1];
            ss[(r0 + g + 8) * BP + col]     = acc[nt][2];
            ss[(r0 + g + 8) * BP + col + 1] = acc[nt][3];
        }
    }
    __syncthreads();

    // softmax rows (scale 1/8 applied here)
    if (tid < 64) {
        float m = -1e30f;
        #pragma unroll 8
        for (int u = 0; u < 64; u++) m = fmaxf(m, ss[tid * BP + u]);
        float s = 0.f;
        float e[64];
        #pragma unroll 8
        for (int u = 0; u < 64; u++) { e[u] = __expf(0.125f * (ss[tid * BP + u] - m)); s += e[u]; }
        float inv = 1.f / s;
        #pragma unroll 8
        for (int u = 0; u < 64; u++) ps[tid * BP + u] = __float2bfloat16(e[u] * inv);
    }
    __syncthreads();

    // ow = P @ V  (A=ps[t][s], B=vT[c][s])  -> store into xs (dead)
    acc_zero(acc);
    gemm64(ps, vT, r0, c0, lane, acc);
    store_bf16(xs, acc, r0, c0, lane);
    __syncthreads();

    // out = ow @ out_w^T + out_b, * gate, write NHWC
    acc_bias(acc, out_b, c0, lane);
    gemm64(xs, wo, r0, c0, lane, acc);
    {
        int g = lane >> 2, tg = lane & 3;
        int t0 = r0 + g, t1 = r0 + g + 8;
        size_t gp0 = ((size_t)(b * HW + h0 + (t0 >> 3)) * HW + (w0 + (t0 & 7))) * (size_t)NC;
        size_t gp1 = ((size_t)(b * HW + h0 + (t1 >> 3)) * HW + (w0 + (t1 & 7))) * (size_t)NC;
        #pragma unroll
        for (int nt = 0; nt < 4; nt++) {
            int col = c0 + nt * 8 + 2 * tg;
            float ga0 = __ldg(&g_gate[b * NC + col]);
            float ga1 = __ldg(&g_gate[b * NC + col + 1]);
            float2 v0 = make_float2(acc[nt][0] * ga0, acc[nt][1] * ga1);
            float2 v1 = make_float2(acc[nt][2] * ga0, acc[nt][3] * ga1);
            *(float2*)(g_A + gp0 + col) = v0;
            *(float2*)(g_A + gp1 + col) = v1;
        }
    }
}

// ============================================================
// K4: 3x3 conv 64->32 (+relu) -> 1x1 32->64, + x + A -> x1 (NHWC)
// 128 threads, 16x16 tile, 2 pixels/thread. stage aliases halo/w1s.
// ============================================================
__global__ void __launch_bounds__(128) k_ms(
        const float* __restrict__ x,
        const float* __restrict__ ms1_w, const float* __restrict__ ms1_b,
        const float* __restrict__ ms2_w, const float* __restrict__ ms2_b) {
    extern __shared__ float sm[];
    float* halo  = sm;             // 16ch * 18*18 = 5184
    float* w1s   = sm + 5184;      // 4608
    float* stage = sm;             // [256][FP] = 16640 (aliases halo+w1s)
    float* w2s   = sm + 16640;     // [64][32]  = 2048
    int tid = threadIdx.x;
    int b = blockIdx.z;
    int gy0 = blockIdx.y << 4, gx0 = blockIdx.x << 4;
    int py = tid >> 4, px = tid & 15;   // py 0..7; handles rows py and py+8

    for (int idx = tid; idx < 2048; idx += 128) w2s[idx] = ms2_w[idx];

    float acc0[32], acc1[32];
    #pragma unroll
    for (int o = 0; o < 32; o++) { acc0[o] = 0.f; acc1[o] = 0.f; }

    for (int ch = 0; ch < 4; ch++) {
        int ic0 = ch << 4;
        __syncthreads();
        for (int idx = tid; idx < 16 * 324; idx += 128) {
            int i = idx / 324, r = idx - i * 324;
            int hy = r / 18, hx = r - hy * 18;
            int gy = gy0 + hy - 1, gx = gx0 + hx - 1;
            float v = 0.f;
            if (gy >= 0 && gy < HW && gx >= 0 && gx < HW)
                v = x[((size_t)(b * NC + ic0 + i)) * PIX + gy * HW + gx];
            halo[idx] = v;
        }
        for (int idx = tid; idx < 4608; idx += 128) {
            int i = idx / 288, r = idx - i * 288;
            int k = r >> 5, o = r & 31;
            w1s[idx] = ms1_w[(size_t)(o * NC + ic0 + i) * 9 + k];
        }
        __syncthreads();
        for (int i = 0; i < 16; i++) {
            #pragma unroll
            for (int k = 0; k < 9; k++) {
                int ky = k / 3, kx = k - ky * 3;
                float xv0 = halo[i * 324 + (py + ky) * 18 + (px + kx)];
                float xv1 = halo[i * 324 + (py + 8 + ky) * 18 + (px + kx)];
                const float4* w4 = (const float4*)&w1s[(i * 9 + k) * 32];
                #pragma unroll
                for (int j = 0; j < 8; j++) {
                    float4 w = w4[j];
                    acc0[4 * j + 0] += xv0 * w.x; acc1[4 * j + 0] += xv1 * w.x;
                    acc0[4 * j + 1] += xv0 * w.y; acc1[4 * j + 1] += xv1 * w.y;
                    acc0[4 * j + 2] += xv0 * w.z; acc1[4 * j + 2] += xv1 * w.z;
                    acc0[4 * j + 3] += xv0 * w.w; acc1[4 * j + 3] += xv1 * w.w;
                }
            }
        }
    }
    __syncthreads();   // all conv reads of halo/w1s done before stage overwrite

    #pragma unroll
    for (int o = 0; o < 32; o++) {
        float bb = __ldg(&ms1_b[o]);
        acc0[o] = fmaxf(acc0[o] + bb, 0.f);
        acc1[o] = fmaxf(acc1[o] + bb, 0.f);
    }
    int p0 = py * 16 + px, p1 = (py + 8) * 16 + px;
    for (int o2 = 0; o2 < 64; o2++) {
        float bb = __ldg(&ms2_b[o2]);
        float s0 = bb, s1 = bb;
        const float4* w4 = (const float4*)&w2s[o2 * 32];
        #pragma unroll
        for (int q = 0; q < 8; q++) {
            float4 w = w4[q];
            s0 += acc0[4 * q + 0] * w.x + acc0[4 * q + 1] * w.y + acc0[4 * q + 2] * w.z + acc0[4 * q + 3] * w.w;
            s1 += acc1[4 * q + 0] * w.x + acc1[4 * q + 1] * w.y + acc1[4 * q + 2] * w.z + acc1[4 * q + 3] * w.w;
        }
        stage[p0 * FP + o2] = s0;
        stage[p1 * FP + o2] = s1;
    }
    for (int c = 0; c < NC; c++) {
        stage[p0 * FP + c] += x[((size_t)(b * NC + c)) * PIX + (gy0 + py) * HW + (gx0 + px)];
        stage[p1 * FP + c] += x[((size_t)(b * NC + c)) * PIX + (gy0 + py + 8) * HW + (gx0 + px)];
    }
    __syncthreads();
    for (int idx = tid; idx < 16384; idx += 128) {
        int p = idx >> 6, c = idx & 63;
        int gy = gy0 + (p >> 4), gx = gx0 + (p & 15);
        size_t g = ((size_t)(b * HW + gy) * HW + gx) * (size_t)NC + c;
        g_x1[g] = stage[p * FP + c] + g_A[g];
    }
}

// ============================================================
// K5: LN + fc1 + GELU + fc2 + residual, tensor-core GEMMs
// ============================================================
__device__ __forceinline__ float gelu_tanh(float v) {
    float u = 0.7978845608028654f * (v + 0.044715f * v * v * v);
    return 0.5f * v * (1.f + tanhf(u));
}

__global__ void __launch_bounds__(256) k_ffn(
        const float* __restrict__ ln_g, const float* __restrict__ ln_b,
        const float* __restrict__ fc1_w, const float* __restrict__ fc1_b,
        const float* __restrict__ fc2_w, const float* __restrict__ fc2_b,
        float* __restrict__ out) {
    extern __shared__ char smc[];
    float*         t  = (float*)smc;                    // [64][FP] fp32 (x1, then out)
    __nv_bfloat16* tn = (__nv_bfloat16*)(smc + 16640);  // [64][BP]
    __nv_bfloat16* w1 = (__nv_bfloat16*)(smc + 25856);
    __nv_bfloat16* h  = (__nv_bfloat16*)(smc + 35072);
    __nv_bfloat16* w2 = (__nv_bfloat16*)(smc + 44288);

    int tid = threadIdx.x;
    int lane = tid & 31, wid = tid >> 5;
    int r0 = (wid >> 1) * 16, c0 = (wid & 1) * 32;
    int blk = blockIdx.x;
    int b = blk >> 10;
    int rem = blk & 1023;
    int hh = rem >> 2;
    int w0 = (rem & 3) << 6;
    size_t base = ((size_t)(b * HW + hh) * HW + w0) * (size_t)NC;

    for (int idx = tid; idx < 4096; idx += 256) {
        t[(idx >> 6) * FP + (idx & 63)] = g_x1[base + idx];
        int o = idx >> 6, c = idx & 63;
        w1[o * BP + c] = __float2bfloat16(fc1_w[idx]);
        w2[o * BP + c] = __float2bfloat16(fc2_w[idx]);
    }
    __syncthreads();
    if (tid < 64) {
        float mu = 0.f;
        #pragma unroll 8
        for (int c = 0; c < NC; c++) mu += t[tid * FP + c];
        mu *= (1.f / NC);
        float var = 0.f;
        #pragma unroll 8
        for (int c = 0; c < NC; c++) { float d = t[tid * FP + c] - mu; var += d * d; }
        var *= (1.f / NC);
        float rs = rsqrtf(var + 1e-5f);
        #pragma unroll 8
        for (int c = 0; c < NC; c++)
            tn[tid * BP + c] = __float2bfloat16(
                (t[tid * FP + c] - mu) * rs * __ldg(&ln_g[c]) + __ldg(&ln_b[c]));
    }
    __syncthreads();

    float acc[4][4];
    acc_bias(acc, fc1_b, c0, lane);
    gemm64(tn, w1, r0, c0, lane, acc);
    #pragma unroll
    for (int nt = 0; nt < 4; nt++)
        #pragma unroll
        for (int i = 0; i < 4; i++) acc[nt][i] = gelu_tanh(acc[nt][i]);
    store_bf16(h, acc, r0, c0, lane);
    __syncthreads();

    acc_bias(acc, fc2_b, c0, lane);
    gemm64(h, w2, r0, c0, lane, acc);
    {   // out = x1 + ffn, in place into t
        int g = lane >> 2, tg = lane & 3;
        #pragma unroll
        for (int nt = 0; nt < 4; nt++) {
            int col = c0 + nt * 8 + 2 * tg;
            t[(r0 + g) * FP + col]     += acc[nt][0];
            t[(r0 + g) * FP + col + 1] += acc[nt][1];
            t[(r0 + g + 8) * FP + col]     += acc[nt][2];
            t[(r0 + g + 8) * FP + col + 1] += acc[nt][3];
        }
    }
    __syncthreads();
    for (int idx = tid; idx < 4096; idx += 256) {
        int c = idx >> 6, p = idx & 63;
        out[((size_t)(b * NC + c)) * PIX + (size_t)hh * HW + w0 + p] = t[p * FP + c];
    }
}

// ============================================================
extern "C" void kernel_launch(void* const* d_in, const int* in_sizes, int n_in,
                              void* d_out, int out_size) {
    const float* x     = (const float*)d_in[0];
    const float* qk_w  = (const float*)d_in[1];
    const float* qk_b  = (const float*)d_in[2];
    const float* v_w   = (const float*)d_in[3];
    const float* v_b   = (const float*)d_in[4];
    const float* out_w = (const float*)d_in[5];
    const float* out_b = (const float*)d_in[6];
    const float* ms1_w = (const float*)d_in[7];
    const float* ms1_b = (const float*)d_in[8];
    const float* ms2_w = (const float*)d_in[9];
    const float* ms2_b = (const float*)d_in[10];
    const float* se1_w = (const float*)d_in[11];
    const float* se1_b = (const float*)d_in[12];
    const float* se2_w = (const float*)d_in[13];
    const float* se2_b = (const float*)d_in[14];
    const float* ln_g  = (const float*)d_in[15];
    const float* ln_b  = (const float*)d_in[16];
    const float* fc1_w = (const float*)d_in[17];
    const float* fc1_b = (const float*)d_in[18];
    const float* fc2_w = (const float*)d_in[19];
    const float* fc2_b = (const float*)d_in[20];
    float* out = (float*)d_out;

    const int smem_attn = 41472 * 2 + 64 * BP * 4;            // bf16 region + fp32 ss = 101376
    const int smem_ms   = (16640 + 2048) * 4;                 // 74752
    const int smem_ffn  = 16640 + 4 * 4608 * 2;               // 53504
    cudaFuncSetAttribute(k_attn, cudaFuncAttributeMaxDynamicSharedMemorySize, smem_attn);
    cudaFuncSetAttribute(k_ms,   cudaFuncAttributeMaxDynamicSharedMemorySize, smem_ms);
    cudaFuncSetAttribute(k_ffn,  cudaFuncAttributeMaxDynamicSharedMemorySize, smem_ffn);

    k_gap<<<NB * NC, 256>>>(x);
    k_gate<<<1, 512>>>(se1_w, se1_b, se2_w, se2_b);
    k_attn<<<8192, 256, smem_attn>>>(x, qk_w, qk_b, v_w, v_b, out_w, out_b);
    k_ms<<<dim3(16, 16, NB), 128, smem_ms>>>(x, ms1_w, ms1_b, ms2_w, ms2_b);
    k_ffn<<<8192, 256, smem_ffn>>>(ln_g, ln_b, fc1_w, fc1_b, fc2_w, fc2_b, out);
}

// round 4
// speedup vs baseline: 2.8271x; 1.7977x over previous
#include <cuda_runtime.h>
#include <cuda_bf16.h>
#include <cstdint>
#include <stdint.h>
#include <math.h>

#define HW   256
#define PIX  65536
#define NB   8
#define NC   64
#define BP   72    // bf16 smem pitch (conflict-free mma frag loads)
#define WP   40    // bf16 pitch for 32-wide k (1x1 conv weights)
#define FP   65    // fp32 smem pitch

// ---- scratch (allocation-free: device globals) ----
__device__ float g_gap[NB * NC];
__device__ float g_gate[NB * NC];
__device__ float g_A[(size_t)NB * PIX * NC];   // gated attn out, NHWC
__device__ float g_x1[(size_t)NB * PIX * NC];  // x + attn + ms, NHWC

// pre-converted bf16 weights
__device__ __align__(16) __nv_bfloat16 g_wq[64 * BP];
__device__ __align__(16) __nv_bfloat16 g_wk[64 * BP];
__device__ __align__(16) __nv_bfloat16 g_wv[64 * BP];
__device__ __align__(16) __nv_bfloat16 g_wo[64 * BP];
__device__ __align__(16) __nv_bfloat16 g_f1[64 * BP];
__device__ __align__(16) __nv_bfloat16 g_f2[64 * BP];
__device__ __align__(16) __nv_bfloat16 g_w1f[9 * 32 * BP];  // [tap][oc][ic]
__device__ __align__(16) __nv_bfloat16 g_w2f[64 * WP];      // [oc][ic(32)]

// ============================================================
// mma helpers
// ============================================================
__device__ __forceinline__ void mma_bf16(float acc[4], uint32_t a0, uint32_t a1,
                                         uint32_t a2, uint32_t a3,
                                         uint32_t b0, uint32_t b1) {
    asm volatile(
        "mma.sync.aligned.m16n8k16.row.col.f32.bf16.bf16.f32 "
        "{%0,%1,%2,%3},{%4,%5,%6,%7},{%8,%9},{%0,%1,%2,%3};"
        : "+f"(acc[0]), "+f"(acc[1]), "+f"(acc[2]), "+f"(acc[3])
        : "r"(a0), "r"(a1), "r"(a2), "r"(a3), "r"(b0), "r"(b1));
}

__device__ __forceinline__ uint32_t pk(float x, float y) {
    __nv_bfloat162 h = __floats2bfloat162_rn(x, y);
    return *(uint32_t*)&h;
}

// C[16 x 64] += A[16 rows from smem, 64k] * B[64n][64k]^T (both pitch BP)
__device__ __forceinline__ void gemm8(const __nv_bfloat16* __restrict__ A,
                                      const __nv_bfloat16* __restrict__ B,
                                      int lane, float acc[8][4]) {
    int g = lane >> 2, tg = lane & 3;
    const __nv_bfloat16* ar = A + g * BP + 2 * tg;
    #pragma unroll
    for (int kt = 0; kt < 4; kt++) {
        uint32_t a0 = *(const uint32_t*)(ar + 16 * kt);
        uint32_t a1 = *(const uint32_t*)(ar + 8 * BP + 16 * kt);
        uint32_t a2 = *(const uint32_t*)(ar + 16 * kt + 8);
        uint32_t a3 = *(const uint32_t*)(ar + 8 * BP + 16 * kt + 8);
        #pragma unroll
        for (int nt = 0; nt < 8; nt++) {
            const __nv_bfloat16* br = B + (8 * nt + g) * BP + 2 * tg + 16 * kt;
            mma_bf16(acc[nt], a0, a1, a2, a3,
                     *(const uint32_t*)br, *(const uint32_t*)(br + 8));
        }
    }
}

// chained: A comes from previous C fragments (register re-pack)
__device__ __forceinline__ void chain8(const float ca[8][4],
                                       const __nv_bfloat16* __restrict__ B,
                                       int lane, float acc[8][4]) {
    int g = lane >> 2, tg = lane & 3;
    #pragma unroll
    for (int kt = 0; kt < 4; kt++) {
        uint32_t a0 = pk(ca[2 * kt][0], ca[2 * kt][1]);
        uint32_t a1 = pk(ca[2 * kt][2], ca[2 * kt][3]);
        uint32_t a2 = pk(ca[2 * kt + 1][0], ca[2 * kt + 1][1]);
        uint32_t a3 = pk(ca[2 * kt + 1][2], ca[2 * kt + 1][3]);
        #pragma unroll
        for (int nt = 0; nt < 8; nt++) {
            const __nv_bfloat16* br = B + (8 * nt + g) * BP + 2 * tg + 16 * kt;
            mma_bf16(acc[nt], a0, a1, a2, a3,
                     *(const uint32_t*)br, *(const uint32_t*)(br + 8));
        }
    }
}

__device__ __forceinline__ void bias8(float acc[8][4], const float* __restrict__ b, int lane) {
    int tg = lane & 3;
    #pragma unroll
    for (int nt = 0; nt < 8; nt++) {
        float b0 = __ldg(b + 8 * nt + 2 * tg);
        float b1 = __ldg(b + 8 * nt + 2 * tg + 1);
        acc[nt][0] = b0; acc[nt][1] = b1; acc[nt][2] = b0; acc[nt][3] = b1;
    }
}

__device__ __forceinline__ void zero8(float acc[8][4]) {
    #pragma unroll
    for (int nt = 0; nt < 8; nt++)
        #pragma unroll
        for (int i = 0; i < 4; i++) acc[nt][i] = 0.f;
}

// store C frags to bf16 smem [row][col] pitch BP
__device__ __forceinline__ void store8(__nv_bfloat16* __restrict__ D,
                                       const float acc[8][4], int lane) {
    int g = lane >> 2, tg = lane & 3;
    #pragma unroll
    for (int nt = 0; nt < 8; nt++) {
        int col = 8 * nt + 2 * tg;
        *(uint32_t*)(D + g * BP + col) = pk(acc[nt][0], acc[nt][1]);
        *(uint32_t*)(D + (g + 8) * BP + col) = pk(acc[nt][2], acc[nt][3]);
    }
}

// ============================================================
// K0: weight pre-conversion to bf16
// ============================================================
__global__ void k_prep(const float* __restrict__ qk_w, const float* __restrict__ v_w,
                       const float* __restrict__ out_w, const float* __restrict__ fc1_w,
                       const float* __restrict__ fc2_w, const float* __restrict__ ms1_w,
                       const float* __restrict__ ms2_w) {
    int n = blockDim.x * gridDim.x;
    int t0 = blockIdx.x * blockDim.x + threadIdx.x;
    for (int idx = t0; idx < 4096; idx += n) {
        int o = idx >> 6, c = idx & 63;
        g_wq[o * BP + c] = __float2bfloat16(qk_w[idx]);
        g_wk[o * BP + c] = __float2bfloat16(qk_w[4096 + idx]);
        g_wv[o * BP + c] = __float2bfloat16(v_w[idx]);
        g_wo[o * BP + c] = __float2bfloat16(out_w[idx]);
        g_f1[o * BP + c] = __float2bfloat16(fc1_w[idx]);
        g_f2[o * BP + c] = __float2bfloat16(fc2_w[idx]);
    }
    for (int idx = t0; idx < 18432; idx += n) {   // ms1_w [32oc][64ic][9]
        int o = idx / 576, r = idx - o * 576;
        int i = r / 9, tap = r - i * 9;
        g_w1f[(tap * 32 + o) * BP + i] = __float2bfloat16(ms1_w[idx]);
    }
    for (int idx = t0; idx < 2048; idx += n) {
        int o = idx >> 5, i = idx & 31;
        g_w2f[o * WP + i] = __float2bfloat16(ms2_w[idx]);
    }
}

// ============================================================
// K1: global average pool per (b,c)
// ============================================================
__global__ void k_gap(const float* __restrict__ x) {
    int bc = blockIdx.x;
    const float4* p = (const float4*)(x + (size_t)bc * PIX);
    float s = 0.f;
    for (int i = threadIdx.x; i < PIX / 4; i += 256) {
        float4 v = p[i];
        s += v.x + v.y + v.z + v.w;
    }
    __shared__ float red[256];
    red[threadIdx.x] = s;
    __syncthreads();
    for (int st = 128; st > 0; st >>= 1) {
        if (threadIdx.x < st) red[threadIdx.x] += red[threadIdx.x + st];
        __syncthreads();
    }
    if (threadIdx.x == 0) g_gap[bc] = red[0] * (1.f / PIX);
}

// ============================================================
// K2: SE gate
// ============================================================
__global__ void k_gate(const float* __restrict__ se1_w, const float* __restrict__ se1_b,
                       const float* __restrict__ se2_w, const float* __restrict__ se2_b) {
    __shared__ float se[NB][4];
    int tid = threadIdx.x;
    if (tid < 32) {
        int b = tid >> 2, j = tid & 3;
        float s = se1_b[j];
        for (int c = 0; c < NC; c++) s += g_gap[b * NC + c] * se1_w[j * NC + c];
        se[b][j] = fmaxf(s, 0.f);
    }
    __syncthreads();
    int b = tid >> 6, o = tid & 63;
    float s = se2_b[o];
    #pragma unroll
    for (int j = 0; j < 4; j++) s += se[b][j] * se2_w[o * 4 + j];
    g_gate[tid] = 1.f / (1.f + __expf(-s));
}

// ============================================================
// K3: window attention, 4 windows/CTA, register-chained mma
// ============================================================
__global__ void __launch_bounds__(256) k_attn(
        const float* __restrict__ x,
        const float* __restrict__ qk_b, const float* __restrict__ v_b,
        const float* __restrict__ out_b) {
    extern __shared__ __nv_bfloat16 sb[];
    __nv_bfloat16* xs = sb;                 // [256 tok][BP]
    __nv_bfloat16* ks = sb + 256 * BP;      // [256 tok][BP]
    __nv_bfloat16* vT = sb + 2 * 256 * BP;  // per window [64 ch][BP tok]
    __nv_bfloat16* wq = sb + 3 * 256 * BP;
    __nv_bfloat16* wk = wq + 64 * BP;
    __nv_bfloat16* wv = wk + 64 * BP;
    __nv_bfloat16* wo = wv + 64 * BP;

    int tid = threadIdx.x, lane = tid & 31, wid = tid >> 5;
    int g = lane >> 2, tg = lane & 3;
    int blk = blockIdx.x;
    int b = blk >> 8, rem = blk & 255;
    int nh = rem >> 3, grp = rem & 7;
    int h0 = nh * 8, gx0 = grp * 32;
    const float* xb = x + (size_t)b * NC * PIX;

    // copy pre-converted weights (uint4)
    for (int i = tid; i < 576; i += 256) {
        ((uint4*)wq)[i] = ((const uint4*)g_wq)[i];
        ((uint4*)wk)[i] = ((const uint4*)g_wk)[i];
        ((uint4*)wv)[i] = ((const uint4*)g_wv)[i];
        ((uint4*)wo)[i] = ((const uint4*)g_wo)[i];
    }
    // load 4 windows of tokens (32-wide strip, coalesced in gmem)
    for (int idx = tid; idx < 16384; idx += 256) {
        int c = idx >> 8, p = idx & 255;
        int ty = p >> 5, r5 = p & 31;
        int w4l = r5 >> 3, tx = r5 & 7;
        int tok = w4l * 64 + ty * 8 + tx;
        xs[tok * BP + c] = __float2bfloat16(xb[(size_t)c * PIX + (h0 + ty) * HW + gx0 + r5]);
    }
    __syncthreads();

    int w4 = wid >> 1, half = wid & 1;
    int Rb = w4 * 64 + half * 32;
    __nv_bfloat16* vw = vT + w4 * 64 * BP;

    // K & V projections -> smem
    #pragma unroll
    for (int mt = 0; mt < 2; mt++) {
        int R = Rb + 16 * mt;
        float acc[8][4];
        bias8(acc, qk_b + 64, lane);
        gemm8(xs + R * BP, wk, lane, acc);
        store8(ks + R * BP, acc, lane);

        bias8(acc, v_b, lane);
        gemm8(xs + R * BP, wv, lane, acc);
        int tI = (R - w4 * 64) + g;
        #pragma unroll
        for (int nt = 0; nt < 8; nt++) {
            int ch = 8 * nt + 2 * tg;
            vw[ch * BP + tI]           = __float2bfloat16(acc[nt][0]);
            vw[(ch + 1) * BP + tI]     = __float2bfloat16(acc[nt][1]);
            vw[ch * BP + tI + 8]       = __float2bfloat16(acc[nt][2]);
            vw[(ch + 1) * BP + tI + 8] = __float2bfloat16(acc[nt][3]);
        }
    }
    __syncthreads();

    #pragma unroll
    for (int mt = 0; mt < 2; mt++) {
        int R = Rb + 16 * mt;
        float qac[8][4];
        bias8(qac, qk_b, lane);
        gemm8(xs + R * BP, wq, lane, qac);

        float sac[8][4];
        zero8(sac);
        chain8(qac, ks + w4 * 64 * BP, lane, sac);   // scores

        // softmax (rows g and g+8), quad reduce
        float mx0 = -1e30f, mx1 = -1e30f;
        #pragma unroll
        for (int nt = 0; nt < 8; nt++) {
            mx0 = fmaxf(mx0, fmaxf(sac[nt][0], sac[nt][1]));
            mx1 = fmaxf(mx1, fmaxf(sac[nt][2], sac[nt][3]));
        }
        mx0 = fmaxf(mx0, __shfl_xor_sync(0xffffffffu, mx0, 1));
        mx0 = fmaxf(mx0, __shfl_xor_sync(0xffffffffu, mx0, 2));
        mx1 = fmaxf(mx1, __shfl_xor_sync(0xffffffffu, mx1, 1));
        mx1 = fmaxf(mx1, __shfl_xor_sync(0xffffffffu, mx1, 2));
        float s0 = 0.f, s1 = 0.f;
        #pragma unroll
        for (int nt = 0; nt < 8; nt++) {
            sac[nt][0] = __expf(0.125f * (sac[nt][0] - mx0)); s0 += sac[nt][0];
            sac[nt][1] = __expf(0.125f * (sac[nt][1] - mx0)); s0 += sac[nt][1];
            sac[nt][2] = __expf(0.125f * (sac[nt][2] - mx1)); s1 += sac[nt][2];
            sac[nt][3] = __expf(0.125f * (sac[nt][3] - mx1)); s1 += sac[nt][3];
        }
        s0 += __shfl_xor_sync(0xffffffffu, s0, 1);
        s0 += __shfl_xor_sync(0xffffffffu, s0, 2);
        s1 += __shfl_xor_sync(0xffffffffu, s1, 1);
        s1 += __shfl_xor_sync(0xffffffffu, s1, 2);
        float i0 = 1.f / s0, i1 = 1.f / s1;
        #pragma unroll
        for (int nt = 0; nt < 8; nt++) {
            sac[nt][0] *= i0; sac[nt][1] *= i0;
            sac[nt][2] *= i1; sac[nt][3] *= i1;
        }

        float oac[8][4];
        zero8(oac);
        chain8(sac, vw, lane, oac);                  // P @ V

        float uac[8][4];
        bias8(uac, out_b, lane);
        chain8(oac, wo, lane, uac);                  // out proj

        // gate + store NHWC
        int t0i = (R - w4 * 64) + g, t1i = t0i + 8;
        size_t p0 = ((size_t)(b * HW + h0 + (t0i >> 3)) * HW + gx0 + w4 * 8 + (t0i & 7)) * (size_t)NC;
        size_t p1 = ((size_t)(b * HW + h0 + (t1i >> 3)) * HW + gx0 + w4 * 8 + (t1i & 7)) * (size_t)NC;
        #pragma unroll
        for (int nt = 0; nt < 8; nt++) {
            int ch = 8 * nt + 2 * tg;
            float ga0 = __ldg(&g_gate[b * NC + ch]);
            float ga1 = __ldg(&g_gate[b * NC + ch + 1]);
            *(float2*)(g_A + p0 + ch) = make_float2(uac[nt][0] * ga0, uac[nt][1] * ga1);
            *(float2*)(g_A + p1 + ch) = make_float2(uac[nt][2] * ga0, uac[nt][3] * ga1);
        }
    }
}

// ============================================================
// K4: 3x3 conv (implicit GEMM, 9 taps) + relu + 1x1 (register
// chained) + x + g_A -> g_x1 NHWC. 16x16 tile, 256 threads.
// ============================================================
__global__ void __launch_bounds__(256) k_ms(
        const float* __restrict__ x,
        const float* __restrict__ ms1_b, const float* __restrict__ ms2_b) {
    extern __shared__ char smc[];
    __nv_bfloat16* halo = (__nv_bfloat16*)smc;          // [324 pix][BP] = 46656B
    float*         stage = (float*)smc;                 // [256][FP] = 66560B (aliases halo)
    __nv_bfloat16* w1 = (__nv_bfloat16*)(smc + 66560);  // 9*32*BP = 41472B
    __nv_bfloat16* w2 = (__nv_bfloat16*)(smc + 108032); // 64*WP*2 = 5120B

    int tid = threadIdx.x, lane = tid & 31, wid = tid >> 5;
    int g = lane >> 2, tg = lane & 3;
    int b = blockIdx.z;
    int gy0 = blockIdx.y << 4, gx0 = blockIdx.x << 4;

    for (int i = tid; i < 2592; i += 256) ((uint4*)w1)[i] = ((const uint4*)g_w1f)[i];
    for (int i = tid; i < 320; i += 256)  ((uint4*)w2)[i] = ((const uint4*)g_w2f)[i];
    // halo load: [hy*18+hx][ch]
    for (int idx = tid; idx < 20736; idx += 256) {
        int c = idx / 324, r = idx - c * 324;
        int hy = r / 18, hx = r - hy * 18;
        int gy = gy0 + hy - 1, gx = gx0 + hx - 1;
        float v = 0.f;
        if (gy >= 0 && gy < HW && gx >= 0 && gx < HW)
            v = x[((size_t)(b * NC + c)) * PIX + (size_t)gy * HW + gx];
        halo[r * BP + c] = __float2bfloat16(v);
    }
    __syncthreads();

    // conv: warp handles tile rows py0, py0+1 (16 pixels each = m16)
    int py0 = wid * 2;
    float cac[2][4][4];
    #pragma unroll
    for (int row = 0; row < 2; row++)
        #pragma unroll
        for (int nt = 0; nt < 4; nt++)
            #pragma unroll
            for (int i = 0; i < 4; i++) cac[row][nt][i] = 0.f;

    #pragma unroll
    for (int tap = 0; tap < 9; tap++) {
        int ky = tap / 3, kx = tap - ky * 3;
        #pragma unroll
        for (int kt = 0; kt < 4; kt++) {
            uint32_t b0[4], b1[4];
            #pragma unroll
            for (int nt = 0; nt < 4; nt++) {
                const __nv_bfloat16* br = w1 + (tap * 32 + 8 * nt + g) * BP + 2 * tg + 16 * kt;
                b0[nt] = *(const uint32_t*)br;
                b1[nt] = *(const uint32_t*)(br + 8);
            }
            #pragma unroll
            for (int row = 0; row < 2; row++) {
                const __nv_bfloat16* ar =
                    halo + ((py0 + row + ky) * 18 + kx + g) * BP + 2 * tg + 16 * kt;
                uint32_t a0 = *(const uint32_t*)ar;
                uint32_t a1 = *(const uint32_t*)(ar + 8 * BP);
                uint32_t a2 = *(const uint32_t*)(ar + 8);
                uint32_t a3 = *(const uint32_t*)(ar + 8 * BP + 8);
                #pragma unroll
                for (int nt = 0; nt < 4; nt++)
                    mma_bf16(cac[row][nt], a0, a1, a2, a3, b0[nt], b1[nt]);
            }
        }
    }
    // relu + bias
    #pragma unroll
    for (int row = 0; row < 2; row++)
        #pragma unroll
        for (int nt = 0; nt < 4; nt++) {
            int ch = 8 * nt + 2 * tg;
            float bb0 = __ldg(&ms1_b[ch]), bb1 = __ldg(&ms1_b[ch + 1]);
            cac[row][nt][0] = fmaxf(cac[row][nt][0] + bb0, 0.f);
            cac[row][nt][1] = fmaxf(cac[row][nt][1] + bb1, 0.f);
            cac[row][nt][2] = fmaxf(cac[row][nt][2] + bb0, 0.f);
            cac[row][nt][3] = fmaxf(cac[row][nt][3] + bb1, 0.f);
        }
    // 1x1 32->64 register-chained
    float dac[2][8][4];
    #pragma unroll
    for (int row = 0; row < 2; row++) bias8(dac[row], ms2_b, lane);
    #pragma unroll
    for (int row = 0; row < 2; row++) {
        #pragma unroll
        for (int kt = 0; kt < 2; kt++) {
            uint32_t a0 = pk(cac[row][2 * kt][0], cac[row][2 * kt][1]);
            uint32_t a1 = pk(cac[row][2 * kt][2], cac[row][2 * kt][3]);
            uint32_t a2 = pk(cac[row][2 * kt + 1][0], cac[row][2 * kt + 1][1]);
            uint32_t a3 = pk(cac[row][2 * kt + 1][2], cac[row][2 * kt + 1][3]);
            #pragma unroll
            for (int nt = 0; nt < 8; nt++) {
                const __nv_bfloat16* br = w2 + (8 * nt + g) * WP + 2 * tg + 16 * kt;
                mma_bf16(dac[row][nt], a0, a1, a2, a3,
                         *(const uint32_t*)br, *(const uint32_t*)(br + 8));
            }
        }
    }
    __syncthreads();   // halo reads done; stage may overwrite
    #pragma unroll
    for (int row = 0; row < 2; row++) {
        int p0 = (py0 + row) * 16 + g, p1 = p0 + 8;
        #pragma unroll
        for (int nt = 0; nt < 8; nt++) {
            int ch = 8 * nt + 2 * tg;
            stage[p0 * FP + ch]     = dac[row][nt][0];
            stage[p0 * FP + ch + 1] = dac[row][nt][1];
            stage[p1 * FP + ch]     = dac[row][nt][2];
            stage[p1 * FP + ch + 1] = dac[row][nt][3];
        }
    }
    __syncthreads();
    {   // + x residual (coalesced per-channel)
        int p = tid, py = p >> 4, px = p & 15;
        const float* xp = x + (size_t)b * NC * PIX + (size_t)(gy0 + py) * HW + gx0 + px;
        for (int c = 0; c < NC; c++) stage[p * FP + c] += xp[(size_t)c * PIX];
    }
    __syncthreads();
    for (int idx = tid; idx < 16384; idx += 256) {
        int p = idx >> 6, c = idx & 63;
        int gy = gy0 + (p >> 4), gx = gx0 + (p & 15);
        size_t gi = ((size_t)(b * HW + gy) * HW + gx) * (size_t)NC + c;
        g_x1[gi] = stage[p * FP + c] + g_A[gi];
    }
}

// ============================================================
// K5: LN + fc1 + GELU + fc2 + residual; 256 pixels (one row)/CTA
// ============================================================
__device__ __forceinline__ float gelu_f(float v) {
    float u = 0.7978845608028654f * (v + 0.044715f * v * v * v);
    return v / (1.f + __expf(-2.f * u));    // == 0.5v(1+tanh(u))
}

__global__ void __launch_bounds__(256) k_ffn(
        const float* __restrict__ ln_g, const float* __restrict__ ln_b,
        const float* __restrict__ fc1_b, const float* __restrict__ fc2_b,
        float* __restrict__ out) {
    extern __shared__ char smc[];
    float*         t  = (float*)smc;                     // [256][FP] = 66560B
    __nv_bfloat16* tn = (__nv_bfloat16*)(smc + 66560);   // [256][BP] = 36864B
    __nv_bfloat16* w1 = (__nv_bfloat16*)(smc + 103424);
    __nv_bfloat16* w2 = (__nv_bfloat16*)(smc + 112640);

    int tid = threadIdx.x, lane = tid & 31, wid = tid >> 5;
    int g = lane >> 2, tg = lane & 3;
    int blk = blockIdx.x;
    int b = blk >> 8, hh = blk & 255;
    size_t base = ((size_t)(b * HW + hh) * HW) * (size_t)NC;

    for (int i = tid; i < 576; i += 256) {
        ((uint4*)w1)[i] = ((const uint4*)g_f1)[i];
        ((uint4*)w2)[i] = ((const uint4*)g_f2)[i];
    }
    for (int idx = tid; idx < 16384; idx += 256)
        t[(idx >> 6) * FP + (idx & 63)] = g_x1[base + idx];
    __syncthreads();
    {   // LN: one pixel per thread
        int p = tid;
        float mu = 0.f;
        #pragma unroll 8
        for (int c = 0; c < NC; c++) mu += t[p * FP + c];
        mu *= (1.f / NC);
        float var = 0.f;
        #pragma unroll 8
        for (int c = 0; c < NC; c++) { float d = t[p * FP + c] - mu; var += d * d; }
        var *= (1.f / NC);
        float rs = rsqrtf(var + 1e-5f);
        #pragma unroll 8
        for (int c = 0; c < NC; c++)
            tn[p * BP + c] = __float2bfloat16(
                (t[p * FP + c] - mu) * rs * __ldg(&ln_g[c]) + __ldg(&ln_b[c]));
    }
    __syncthreads();

    #pragma unroll
    for (int mt = 0; mt < 2; mt++) {
        int R = wid * 32 + 16 * mt;
        float fac[8][4];
        bias8(fac, fc1_b, lane);
        gemm8(tn + R * BP, w1, lane, fac);
        #pragma unroll
        for (int nt = 0; nt < 8; nt++)
            #pragma unroll
            for (int i = 0; i < 4; i++) fac[nt][i] = gelu_f(fac[nt][i]);
        float gac[8][4];
        bias8(gac, fc2_b, lane);
        chain8(fac, w2, lane, gac);
        // residual + store NCHW
        int p0 = R + g, p1 = p0 + 8;
        #pragma unroll
        for (int nt = 0; nt < 8; nt++) {
            int ch = 8 * nt + 2 * tg;
            float r00 = t[p0 * FP + ch], r01 = t[p0 * FP + ch + 1];
            float r10 = t[p1 * FP + ch], r11 = t[p1 * FP + ch + 1];
            size_t o0 = ((size_t)(b * NC + ch)) * PIX + (size_t)hh * HW;
            size_t o1 = ((size_t)(b * NC + ch + 1)) * PIX + (size_t)hh * HW;
            out[o0 + p0] = gac[nt][0] + r00;
            out[o1 + p0] = gac[nt][1] + r01;
            out[o0 + p1] = gac[nt][2] + r10;
            out[o1 + p1] = gac[nt][3] + r11;
        }
    }
}

// ============================================================
extern "C" void kernel_launch(void* const* d_in, const int* in_sizes, int n_in,
                              void* d_out, int out_size) {
    const float* x     = (const float*)d_in[0];
    const float* qk_w  = (const float*)d_in[1];
    const float* qk_b  = (const float*)d_in[2];
    const float* v_w   = (const float*)d_in[3];
    const float* v_b   = (const float*)d_in[4];
    const float* out_w = (const float*)d_in[5];
    const float* out_b = (const float*)d_in[6];
    const float* ms1_w = (const float*)d_in[7];
    const float* ms1_b = (const float*)d_in[8];
    const float* ms2_w = (const float*)d_in[9];
    const float* ms2_b = (const float*)d_in[10];
    const float* se1_w = (const float*)d_in[11];
    const float* se1_b = (const float*)d_in[12];
    const float* se2_w = (const float*)d_in[13];
    const float* se2_b = (const float*)d_in[14];
    const float* ln_g  = (const float*)d_in[15];
    const float* ln_b  = (const float*)d_in[16];
    const float* fc1_w = (const float*)d_in[17];
    const float* fc1_b = (const float*)d_in[18];
    const float* fc2_w = (const float*)d_in[19];
    const float* fc2_b = (const float*)d_in[20];
    float* out = (float*)d_out;

    const int smem_attn = 3 * 256 * BP * 2 + 4 * 64 * BP * 2;   // 147456
    const int smem_ms   = 66560 + 41472 + 5120;                 // 113152
    const int smem_ffn  = 66560 + 36864 + 2 * 9216;             // 121856
    cudaFuncSetAttribute(k_attn, cudaFuncAttributeMaxDynamicSharedMemorySize, smem_attn);
    cudaFuncSetAttribute(k_ms,   cudaFuncAttributeMaxDynamicSharedMemorySize, smem_ms);
    cudaFuncSetAttribute(k_ffn,  cudaFuncAttributeMaxDynamicSharedMemorySize, smem_ffn);

    k_prep<<<48, 256>>>(qk_w, v_w, out_w, fc1_w, fc2_w, ms1_w, ms2_w);
    k_gap<<<NB * NC, 256>>>(x);
    k_gate<<<1, 512>>>(se1_w, se1_b, se2_w, se2_b);
    k_attn<<<2048, 256, smem_attn>>>(x, qk_b, v_b, out_b);
    k_ms<<<dim3(16, 16, NB), 256, smem_ms>>>(x, ms1_b, ms2_b);
    k_ffn<<<2048, 256, smem_ffn>>>(ln_g, ln_b, fc1_b, fc2_b, out);
}

// round 5
// speedup vs baseline: 4.6151x; 1.6324x over previous
#include <cuda_runtime.h>
#include <cuda_bf16.h>
#include <cstdint>
#include <stdint.h>
#include <math.h>

#define HW   256
#define PIX  65536
#define NB   8
#define NC   64
#define BP   72    // bf16 smem pitch (conflict-free mma frag loads)
#define FP   65    // fp32 smem pitch

// ---- scratch (allocation-free: device globals) ----
__device__ float g_gap[NB * NC];
__device__ float g_gate[NB * NC];
__device__ float g_A[(size_t)NB * PIX * NC];   // gated attn out, NHWC

// fragment-packed bf16 weights: uint2 per (kt*NT+nt)*32+lane
__device__ __align__(16) uint2 g_wqf[1024];
__device__ __align__(16) uint2 g_wkf[1024];
__device__ __align__(16) uint2 g_wvf[1024];
__device__ __align__(16) uint2 g_wof[1024];
__device__ __align__(16) uint2 g_f1f[1024];
__device__ __align__(16) uint2 g_f2f[1024];
__device__ __align__(16) uint2 g_w1f[9 * 512];  // conv 3x3: per tap, kt<4, nt<4
__device__ __align__(16) uint2 g_w2f[512];      // 1x1 32->64: kt<2, nt<8

// ============================================================
// mma helpers
// ============================================================
__device__ __forceinline__ void mma_bf16(float acc[4], uint32_t a0, uint32_t a1,
                                         uint32_t a2, uint32_t a3,
                                         uint32_t b0, uint32_t b1) {
    asm volatile(
        "mma.sync.aligned.m16n8k16.row.col.f32.bf16.bf16.f32 "
        "{%0,%1,%2,%3},{%4,%5,%6,%7},{%8,%9},{%0,%1,%2,%3};"
        : "+f"(acc[0]), "+f"(acc[1]), "+f"(acc[2]), "+f"(acc[3])
        : "r"(a0), "r"(a1), "r"(a2), "r"(a3), "r"(b0), "r"(b1));
}

__device__ __forceinline__ uint32_t pk(float x, float y) {
    __nv_bfloat162 h = __floats2bfloat162_rn(x, y);
    return *(uint32_t*)&h;
}

// C[16 x 64] += A(smem rows, pitch BP) * B(fragment-packed gmem)
__device__ __forceinline__ void gemm8_g(const __nv_bfloat16* __restrict__ A,
                                        const uint2* __restrict__ Bf,
                                        int lane, float acc[8][4]) {
    int g = lane >> 2, tg = lane & 3;
    const __nv_bfloat16* ar = A + g * BP + 2 * tg;
    #pragma unroll
    for (int kt = 0; kt < 4; kt++) {
        uint32_t a0 = *(const uint32_t*)(ar + 16 * kt);
        uint32_t a1 = *(const uint32_t*)(ar + 8 * BP + 16 * kt);
        uint32_t a2 = *(const uint32_t*)(ar + 16 * kt + 8);
        uint32_t a3 = *(const uint32_t*)(ar + 8 * BP + 16 * kt + 8);
        #pragma unroll
        for (int nt = 0; nt < 8; nt++) {
            uint2 b = __ldg(&Bf[(kt * 8 + nt) * 32 + lane]);
            mma_bf16(acc[nt], a0, a1, a2, a3, b.x, b.y);
        }
    }
}

// chained, B from smem (pitch BP)
__device__ __forceinline__ void chain8(const float ca[8][4],
                                       const __nv_bfloat16* __restrict__ B,
                                       int lane, float acc[8][4]) {
    int g = lane >> 2, tg = lane & 3;
    #pragma unroll
    for (int kt = 0; kt < 4; kt++) {
        uint32_t a0 = pk(ca[2 * kt][0], ca[2 * kt][1]);
        uint32_t a1 = pk(ca[2 * kt][2], ca[2 * kt][3]);
        uint32_t a2 = pk(ca[2 * kt + 1][0], ca[2 * kt + 1][1]);
        uint32_t a3 = pk(ca[2 * kt + 1][2], ca[2 * kt + 1][3]);
        #pragma unroll
        for (int nt = 0; nt < 8; nt++) {
            const __nv_bfloat16* br = B + (8 * nt + g) * BP + 2 * tg + 16 * kt;
            mma_bf16(acc[nt], a0, a1, a2, a3,
                     *(const uint32_t*)br, *(const uint32_t*)(br + 8));
        }
    }
}

// chained, B fragment-packed gmem
__device__ __forceinline__ void chain8_g(const float ca[8][4],
                                         const uint2* __restrict__ Bf,
                                         int lane, float acc[8][4]) {
    #pragma unroll
    for (int kt = 0; kt < 4; kt++) {
        uint32_t a0 = pk(ca[2 * kt][0], ca[2 * kt][1]);
        uint32_t a1 = pk(ca[2 * kt][2], ca[2 * kt][3]);
        uint32_t a2 = pk(ca[2 * kt + 1][0], ca[2 * kt + 1][1]);
        uint32_t a3 = pk(ca[2 * kt + 1][2], ca[2 * kt + 1][3]);
        #pragma unroll
        for (int nt = 0; nt < 8; nt++) {
            uint2 b = __ldg(&Bf[(kt * 8 + nt) * 32 + lane]);
            mma_bf16(acc[nt], a0, a1, a2, a3, b.x, b.y);
        }
    }
}

__device__ __forceinline__ void bias8(float acc[8][4], const float* __restrict__ b, int lane) {
    int tg = lane & 3;
    #pragma unroll
    for (int nt = 0; nt < 8; nt++) {
        float b0 = __ldg(b + 8 * nt + 2 * tg);
        float b1 = __ldg(b + 8 * nt + 2 * tg + 1);
        acc[nt][0] = b0; acc[nt][1] = b1; acc[nt][2] = b0; acc[nt][3] = b1;
    }
}

__device__ __forceinline__ void zero8(float acc[8][4]) {
    #pragma unroll
    for (int nt = 0; nt < 8; nt++)
        #pragma unroll
        for (int i = 0; i < 4; i++) acc[nt][i] = 0.f;
}

__device__ __forceinline__ void store8(__nv_bfloat16* __restrict__ D,
                                       const float acc[8][4], int lane) {
    int g = lane >> 2, tg = lane & 3;
    #pragma unroll
    for (int nt = 0; nt < 8; nt++) {
        int col = 8 * nt + 2 * tg;
        *(uint32_t*)(D + g * BP + col) = pk(acc[nt][0], acc[nt][1]);
        *(uint32_t*)(D + (g + 8) * BP + col) = pk(acc[nt][2], acc[nt][3]);
    }
}

// ============================================================
// K0: pack weights into mma-fragment order (bf16 pairs)
// ============================================================
__global__ void k_prep(const float* __restrict__ qk_w, const float* __restrict__ v_w,
                       const float* __restrict__ out_w, const float* __restrict__ fc1_w,
                       const float* __restrict__ fc2_w, const float* __restrict__ ms1_w,
                       const float* __restrict__ ms2_w) {
    int n = blockDim.x * gridDim.x;
    int t0 = blockIdx.x * blockDim.x + threadIdx.x;
    // 64x64 matrices (kt<4, nt<8)
    for (int idx = t0; idx < 1024; idx += n) {
        int kt = idx >> 8, r = idx & 255;
        int nt = r >> 5, lane = r & 31;
        int g = lane >> 2, tg = lane & 3;
        int row = 8 * nt + g, col = 2 * tg + 16 * kt;
        #define PACK64(W) make_uint2(pk((W)[row * 64 + col], (W)[row * 64 + col + 1]), \
                                     pk((W)[row * 64 + col + 8], (W)[row * 64 + col + 9]))
        g_wqf[idx] = PACK64(qk_w);
        g_wkf[idx] = PACK64(qk_w + 4096);
        g_wvf[idx] = PACK64(v_w);
        g_wof[idx] = PACK64(out_w);
        g_f1f[idx] = PACK64(fc1_w);
        g_f2f[idx] = PACK64(fc2_w);
        #undef PACK64
    }
    // conv 3x3: ms1_w [32 o][64 i][9 tap]; frag per tap: kt<4, nt<4
    for (int idx = t0; idx < 9 * 512; idx += n) {
        int tap = idx >> 9, r = idx & 511;
        int kt = r >> 7, r2 = r & 127;
        int nt = r2 >> 5, lane = r2 & 31;
        int g = lane >> 2, tg = lane & 3;
        int row = 8 * nt + g, col = 2 * tg + 16 * kt;
        uint2 u;
        u.x = pk(ms1_w[(row * 64 + col) * 9 + tap],     ms1_w[(row * 64 + col + 1) * 9 + tap]);
        u.y = pk(ms1_w[(row * 64 + col + 8) * 9 + tap], ms1_w[(row * 64 + col + 9) * 9 + tap]);
        g_w1f[idx] = u;
    }
    // 1x1: ms2_w [64 o][32 i]; kt<2, nt<8
    for (int idx = t0; idx < 512; idx += n) {
        int kt = idx >> 8, r = idx & 255;
        int nt = r >> 5, lane = r & 31;
        int g = lane >> 2, tg = lane & 3;
        int row = 8 * nt + g, col = 2 * tg + 16 * kt;
        uint2 u;
        u.x = pk(ms2_w[row * 32 + col],     ms2_w[row * 32 + col + 1]);
        u.y = pk(ms2_w[row * 32 + col + 8], ms2_w[row * 32 + col + 9]);
        g_w2f[idx] = u;
    }
}

// ============================================================
// K1: global average pool per (b,c)
// ============================================================
__global__ void k_gap(const float* __restrict__ x) {
    int bc = blockIdx.x;
    const float4* p = (const float4*)(x + (size_t)bc * PIX);
    float s = 0.f;
    for (int i = threadIdx.x; i < PIX / 4; i += 256) {
        float4 v = p[i];
        s += v.x + v.y + v.z + v.w;
    }
    __shared__ float red[256];
    red[threadIdx.x] = s;
    __syncthreads();
    for (int st = 128; st > 0; st >>= 1) {
        if (threadIdx.x < st) red[threadIdx.x] += red[threadIdx.x + st];
        __syncthreads();
    }
    if (threadIdx.x == 0) g_gap[bc] = red[0] * (1.f / PIX);
}

// ============================================================
// K2: SE gate
// ============================================================
__global__ void k_gate(const float* __restrict__ se1_w, const float* __restrict__ se1_b,
                       const float* __restrict__ se2_w, const float* __restrict__ se2_b) {
    __shared__ float se[NB][4];
    int tid = threadIdx.x;
    if (tid < 32) {
        int b = tid >> 2, j = tid & 3;
        float s = se1_b[j];
        for (int c = 0; c < NC; c++) s += g_gap[b * NC + c] * se1_w[j * NC + c];
        se[b][j] = fmaxf(s, 0.f);
    }
    __syncthreads();
    int b = tid >> 6, o = tid & 63;
    float s = se2_b[o];
    #pragma unroll
    for (int j = 0; j < 4; j++) s += se[b][j] * se2_w[o * 4 + j];
    g_gate[tid] = 1.f / (1.f + __expf(-s));
}

// ============================================================
// K3: window attention, 4 windows/CTA, weights from gmem frags
// ============================================================
__global__ void __launch_bounds__(256, 2) k_attn(
        const float* __restrict__ x,
        const float* __restrict__ qk_b, const float* __restrict__ v_b,
        const float* __restrict__ out_b) {
    extern __shared__ __nv_bfloat16 sb[];
    __nv_bfloat16* xs = sb;                 // [256 tok][BP]
    __nv_bfloat16* ks = sb + 256 * BP;      // [256 tok][BP]
    __nv_bfloat16* vT = sb + 2 * 256 * BP;  // per window [64 ch][BP tok]

    int tid = threadIdx.x, lane = tid & 31, wid = tid >> 5;
    int g = lane >> 2, tg = lane & 3;
    int blk = blockIdx.x;
    int b = blk >> 8, rem = blk & 255;
    int nh = rem >> 3, grp = rem & 7;
    int h0 = nh * 8, gx0 = grp * 32;
    const float* xb = x + (size_t)b * NC * PIX;

    // load 4 windows of tokens (32-wide strip, coalesced)
    for (int idx = tid; idx < 16384; idx += 256) {
        int c = idx >> 8, p = idx & 255;
        int ty = p >> 5, r5 = p & 31;
        int w4l = r5 >> 3, tx = r5 & 7;
        int tok = w4l * 64 + ty * 8 + tx;
        xs[tok * BP + c] = __float2bfloat16(xb[(size_t)c * PIX + (h0 + ty) * HW + gx0 + r5]);
    }
    __syncthreads();

    int w4 = wid >> 1, half = wid & 1;
    int Rb = w4 * 64 + half * 32;
    __nv_bfloat16* vw = vT + w4 * 64 * BP;

    // K & V projections -> smem
    #pragma unroll
    for (int mt = 0; mt < 2; mt++) {
        int R = Rb + 16 * mt;
        float acc[8][4];
        bias8(acc, qk_b + 64, lane);
        gemm8_g(xs + R * BP, g_wkf, lane, acc);
        store8(ks + R * BP, acc, lane);

        bias8(acc, v_b, lane);
        gemm8_g(xs + R * BP, g_wvf, lane, acc);
        int tI = (R - w4 * 64) + g;
        #pragma unroll
        for (int nt = 0; nt < 8; nt++) {
            int ch = 8 * nt + 2 * tg;
            vw[ch * BP + tI]           = __float2bfloat16(acc[nt][0]);
            vw[(ch + 1) * BP + tI]     = __float2bfloat16(acc[nt][1]);
            vw[ch * BP + tI + 8]       = __float2bfloat16(acc[nt][2]);
            vw[(ch + 1) * BP + tI + 8] = __float2bfloat16(acc[nt][3]);
        }
    }
    __syncthreads();

    #pragma unroll
    for (int mt = 0; mt < 2; mt++) {
        int R = Rb + 16 * mt;
        float qac[8][4];
        bias8(qac, qk_b, lane);
        gemm8_g(xs + R * BP, g_wqf, lane, qac);

        float sac[8][4];
        zero8(sac);
        chain8(qac, ks + w4 * 64 * BP, lane, sac);   // scores

        float mx0 = -1e30f, mx1 = -1e30f;
        #pragma unroll
        for (int nt = 0; nt < 8; nt++) {
            mx0 = fmaxf(mx0, fmaxf(sac[nt][0], sac[nt][1]));
            mx1 = fmaxf(mx1, fmaxf(sac[nt][2], sac[nt][3]));
        }
        mx0 = fmaxf(mx0, __shfl_xor_sync(0xffffffffu, mx0, 1));
        mx0 = fmaxf(mx0, __shfl_xor_sync(0xffffffffu, mx0, 2));
        mx1 = fmaxf(mx1, __shfl_xor_sync(0xffffffffu, mx1, 1));
        mx1 = fmaxf(mx1, __shfl_xor_sync(0xffffffffu, mx1, 2));
        float s0 = 0.f, s1 = 0.f;
        #pragma unroll
        for (int nt = 0; nt < 8; nt++) {
            sac[nt][0] = __expf(0.125f * (sac[nt][0] - mx0)); s0 += sac[nt][0];
            sac[nt][1] = __expf(0.125f * (sac[nt][1] - mx0)); s0 += sac[nt][1];
            sac[nt][2] = __expf(0.125f * (sac[nt][2] - mx1)); s1 += sac[nt][2];
            sac[nt][3] = __expf(0.125f * (sac[nt][3] - mx1)); s1 += sac[nt][3];
        }
        s0 += __shfl_xor_sync(0xffffffffu, s0, 1);
        s0 += __shfl_xor_sync(0xffffffffu, s0, 2);
        s1 += __shfl_xor_sync(0xffffffffu, s1, 1);
        s1 += __shfl_xor_sync(0xffffffffu, s1, 2);
        float i0 = 1.f / s0, i1 = 1.f / s1;
        #pragma unroll
        for (int nt = 0; nt < 8; nt++) {
            sac[nt][0] *= i0; sac[nt][1] *= i0;
            sac[nt][2] *= i1; sac[nt][3] *= i1;
        }

        float oac[8][4];
        zero8(oac);
        chain8(sac, vw, lane, oac);                  // P @ V

        float uac[8][4];
        bias8(uac, out_b, lane);
        chain8_g(oac, g_wof, lane, uac);             // out proj

        int t0i = (R - w4 * 64) + g, t1i = t0i + 8;
        size_t p0 = ((size_t)(b * HW + h0 + (t0i >> 3)) * HW + gx0 + w4 * 8 + (t0i & 7)) * (size_t)NC;
        size_t p1 = ((size_t)(b * HW + h0 + (t1i >> 3)) * HW + gx0 + w4 * 8 + (t1i & 7)) * (size_t)NC;
        #pragma unroll
        for (int nt = 0; nt < 8; nt++) {
            int ch = 8 * nt + 2 * tg;
            float ga0 = __ldg(&g_gate[b * NC + ch]);
            float ga1 = __ldg(&g_gate[b * NC + ch + 1]);
            *(float2*)(g_A + p0 + ch) = make_float2(uac[nt][0] * ga0, uac[nt][1] * ga1);
            *(float2*)(g_A + p1 + ch) = make_float2(uac[nt][2] * ga0, uac[nt][3] * ga1);
        }
    }
}

// ============================================================
// K4 (fused tail): 3x3 conv (tensor implicit GEMM) + relu +
// 1x1 chain + x + g_A -> x1 (smem) -> LN -> fc1+GELU -> fc2
// + residual -> out (NCHW). One 16x16 tile / CTA.
// ============================================================
__device__ __forceinline__ float gelu_f(float v) {
    float u = 0.7978845608028654f * (v + 0.044715f * v * v * v);
    return v / (1.f + __expf(-2.f * u));
}

__global__ void __launch_bounds__(256, 2) k_tail(
        const float* __restrict__ x,
        const float* __restrict__ ms1_b, const float* __restrict__ ms2_b,
        const float* __restrict__ ln_g, const float* __restrict__ ln_b,
        const float* __restrict__ fc1_b, const float* __restrict__ fc2_b,
        float* __restrict__ out) {
    extern __shared__ char smc[];
    __nv_bfloat16* halo  = (__nv_bfloat16*)smc;           // [324][BP] = 46656B
    float*         stage = (float*)smc;                   // [256][FP] = 66560B (aliases halo)
    __nv_bfloat16* tn    = (__nv_bfloat16*)(smc + 66560); // [256][BP] = 36864B

    int tid = threadIdx.x, lane = tid & 31, wid = tid >> 5;
    int g = lane >> 2, tg = lane & 3;
    int b = blockIdx.z;
    int gy0 = blockIdx.y << 4, gx0 = blockIdx.x << 4;

    // halo load: [hy*18+hx][ch]
    for (int idx = tid; idx < 20736; idx += 256) {
        int c = idx / 324, r = idx - c * 324;
        int hy = r / 18, hx = r - hy * 18;
        int gy = gy0 + hy - 1, gx = gx0 + hx - 1;
        float v = 0.f;
        if (gy >= 0 && gy < HW && gx >= 0 && gx < HW)
            v = x[((size_t)(b * NC + c)) * PIX + (size_t)gy * HW + gx];
        halo[r * BP + c] = __float2bfloat16(v);
    }
    __syncthreads();

    // conv: warp handles tile rows py0, py0+1
    int py0 = wid * 2;
    float cac[2][4][4];
    #pragma unroll
    for (int row = 0; row < 2; row++)
        #pragma unroll
        for (int nt = 0; nt < 4; nt++)
            #pragma unroll
            for (int i = 0; i < 4; i++) cac[row][nt][i] = 0.f;

    #pragma unroll
    for (int tap = 0; tap < 9; tap++) {
        int ky = tap / 3, kx = tap - ky * 3;
        #pragma unroll
        for (int kt = 0; kt < 4; kt++) {
            uint2 bf[4];
            #pragma unroll
            for (int nt = 0; nt < 4; nt++)
                bf[nt] = __ldg(&g_w1f[tap * 512 + (kt * 4 + nt) * 32 + lane]);
            #pragma unroll
            for (int row = 0; row < 2; row++) {
                const __nv_bfloat16* ar =
                    halo + ((py0 + row + ky) * 18 + kx + g) * BP + 2 * tg + 16 * kt;
                uint32_t a0 = *(const uint32_t*)ar;
                uint32_t a1 = *(const uint32_t*)(ar + 8 * BP);
                uint32_t a2 = *(const uint32_t*)(ar + 8);
                uint32_t a3 = *(const uint32_t*)(ar + 8 * BP + 8);
                #pragma unroll
                for (int nt = 0; nt < 4; nt++)
                    mma_bf16(cac[row][nt], a0, a1, a2, a3, bf[nt].x, bf[nt].y);
            }
        }
    }
    // relu + bias
    #pragma unroll
    for (int row = 0; row < 2; row++)
        #pragma unroll
        for (int nt = 0; nt < 4; nt++) {
            int ch = 8 * nt + 2 * tg;
            float bb0 = __ldg(&ms1_b[ch]), bb1 = __ldg(&ms1_b[ch + 1]);
            cac[row][nt][0] = fmaxf(cac[row][nt][0] + bb0, 0.f);
            cac[row][nt][1] = fmaxf(cac[row][nt][1] + bb1, 0.f);
            cac[row][nt][2] = fmaxf(cac[row][nt][2] + bb0, 0.f);
            cac[row][nt][3] = fmaxf(cac[row][nt][3] + bb1, 0.f);
        }
    // 1x1 32->64 register-chained
    float dac[2][8][4];
    #pragma unroll
    for (int row = 0; row < 2; row++) bias8(dac[row], ms2_b, lane);
    #pragma unroll
    for (int row = 0; row < 2; row++) {
        #pragma unroll
        for (int kt = 0; kt < 2; kt++) {
            uint32_t a0 = pk(cac[row][2 * kt][0], cac[row][2 * kt][1]);
            uint32_t a1 = pk(cac[row][2 * kt][2], cac[row][2 * kt][3]);
            uint32_t a2 = pk(cac[row][2 * kt + 1][0], cac[row][2 * kt + 1][1]);
            uint32_t a3 = pk(cac[row][2 * kt + 1][2], cac[row][2 * kt + 1][3]);
            #pragma unroll
            for (int nt = 0; nt < 8; nt++) {
                uint2 bfr = __ldg(&g_w2f[(kt * 8 + nt) * 32 + lane]);
                mma_bf16(dac[row][nt], a0, a1, a2, a3, bfr.x, bfr.y);
            }
        }
    }
    __syncthreads();   // all halo reads done; stage may overwrite
    #pragma unroll
    for (int row = 0; row < 2; row++) {
        int p0 = (py0 + row) * 16 + g, p1 = p0 + 8;
        #pragma unroll
        for (int nt = 0; nt < 8; nt++) {
            int ch = 8 * nt + 2 * tg;
            stage[p0 * FP + ch]     = dac[row][nt][0];
            stage[p0 * FP + ch + 1] = dac[row][nt][1];
            stage[p1 * FP + ch]     = dac[row][nt][2];
            stage[p1 * FP + ch + 1] = dac[row][nt][3];
        }
    }
    __syncthreads();
    {   // + x residual (fp32, per-channel coalesced)
        int p = tid, py = p >> 4, px = p & 15;
        const float* xp = x + (size_t)b * NC * PIX + (size_t)(gy0 + py) * HW + gx0 + px;
        #pragma unroll 8
        for (int c = 0; c < NC; c++) stage[p * FP + c] += xp[(size_t)c * PIX];
    }
    __syncthreads();
    // + attention residual (g_A NHWC, coalesced)
    for (int idx = tid; idx < 16384; idx += 256) {
        int p = idx >> 6, c = idx & 63;
        int gy = gy0 + (p >> 4), gx = gx0 + (p & 15);
        size_t gi = ((size_t)(b * HW + gy) * HW + gx) * (size_t)NC + c;
        stage[p * FP + c] += g_A[gi];
    }
    __syncthreads();
    {   // LN per pixel -> tn (bf16)
        int p = tid;
        float mu = 0.f;
        #pragma unroll 8
        for (int c = 0; c < NC; c++) mu += stage[p * FP + c];
        mu *= (1.f / NC);
        float var = 0.f;
        #pragma unroll 8
        for (int c = 0; c < NC; c++) { float d = stage[p * FP + c] - mu; var += d * d; }
        var *= (1.f / NC);
        float rs = rsqrtf(var + 1e-5f);
        #pragma unroll 8
        for (int c = 0; c < NC; c++)
            tn[p * BP + c] = __float2bfloat16(
                (stage[p * FP + c] - mu) * rs * __ldg(&ln_g[c]) + __ldg(&ln_b[c]));
    }
    __syncthreads();

    // FFN: fc1 + GELU + fc2 + residual; write out NCHW
    #pragma unroll
    for (int mt = 0; mt < 2; mt++) {
        int R = wid * 32 + 16 * mt;
        float fac[8][4];
        bias8(fac, fc1_b, lane);
        gemm8_g(tn + R * BP, g_f1f, lane, fac);
        #pragma unroll
        for (int nt = 0; nt < 8; nt++)
            #pragma unroll
            for (int i = 0; i < 4; i++) fac[nt][i] = gelu_f(fac[nt][i]);
        float gac[8][4];
        bias8(gac, fc2_b, lane);
        chain8_g(fac, g_f2f, lane, gac);

        int p0 = R + g, p1 = p0 + 8;
        int py0o = p0 >> 4, px0o = p0 & 15;
        int py1o = p1 >> 4, px1o = p1 & 15;
        #pragma unroll
        for (int nt = 0; nt < 8; nt++) {
            int ch = 8 * nt + 2 * tg;
            size_t o0 = ((size_t)(b * NC + ch)) * PIX;
            size_t o1 = ((size_t)(b * NC + ch + 1)) * PIX;
            out[o0 + (size_t)(gy0 + py0o) * HW + gx0 + px0o] = gac[nt][0] + stage[p0 * FP + ch];
            out[o1 + (size_t)(gy0 + py0o) * HW + gx0 + px0o] = gac[nt][1] + stage[p0 * FP + ch + 1];
            out[o0 + (size_t)(gy0 + py1o) * HW + gx0 + px1o] = gac[nt][2] + stage[p1 * FP + ch];
            out[o1 + (size_t)(gy0 + py1o) * HW + gx0 + px1o] = gac[nt][3] + stage[p1 * FP + ch + 1];
        }
    }
}

// ============================================================
extern "C" void kernel_launch(void* const* d_in, const int* in_sizes, int n_in,
                              void* d_out, int out_size) {
    const float* x     = (const float*)d_in[0];
    const float* qk_w  = (const float*)d_in[1];
    const float* qk_b  = (const float*)d_in[2];
    const float* v_w   = (const float*)d_in[3];
    const float* v_b   = (const float*)d_in[4];
    const float* out_w = (const float*)d_in[5];
    const float* out_b = (const float*)d_in[6];
    const float* ms1_w = (const float*)d_in[7];
    const float* ms1_b = (const float*)d_in[8];
    const float* ms2_w = (const float*)d_in[9];
    const float* ms2_b = (const float*)d_in[10];
    const float* se1_w = (const float*)d_in[11];
    const float* se1_b = (const float*)d_in[12];
    const float* se2_w = (const float*)d_in[13];
    const float* se2_b = (const float*)d_in[14];
    const float* ln_g  = (const float*)d_in[15];
    const float* ln_b  = (const float*)d_in[16];
    const float* fc1_w = (const float*)d_in[17];
    const float* fc1_b = (const float*)d_in[18];
    const float* fc2_w = (const float*)d_in[19];
    const float* fc2_b = (const float*)d_in[20];
    float* out = (float*)d_out;

    const int smem_attn = 3 * 256 * BP * 2;        // 110592
    const int smem_tail = 66560 + 36864;           // 103424
    cudaFuncSetAttribute(k_attn, cudaFuncAttributeMaxDynamicSharedMemorySize, smem_attn);
    cudaFuncSetAttribute(k_tail, cudaFuncAttributeMaxDynamicSharedMemorySize, smem_tail);

    k_prep<<<24, 256>>>(qk_w, v_w, out_w, fc1_w, fc2_w, ms1_w, ms2_w);
    k_gap<<<NB * NC, 256>>>(x);
    k_gate<<<1, 512>>>(se1_w, se1_b, se2_w, se2_b);
    k_attn<<<2048, 256, smem_attn>>>(x, qk_b, v_b, out_b);
    k_tail<<<dim3(16, 16, NB), 256, smem_tail>>>(x, ms1_b, ms2_b, ln_g, ln_b,
                                                 fc1_b, fc2_b, out);
}

// round 6
// speedup vs baseline: 4.6798x; 1.0140x over previous
#include <cuda_runtime.h>
#include <cuda_bf16.h>
#include <cstdint>
#include <stdint.h>
#include <math.h>

#define HW   256
#define PIX  65536
#define NB   8
#define NC   64
#define BP   72    // bf16 smem pitch (conflict-free mma frag loads)
#define FP   65    // fp32 smem pitch

// ---- scratch (allocation-free: device globals) ----
__device__ float g_gap[NB * NC];
__device__ float g_gate[NB * NC];
__device__ float g_A[(size_t)NB * PIX * NC];   // gated attn out, NHWC

// fragment-packed bf16 weights: uint2 per (kt*NT+nt)*32+lane
__device__ __align__(16) uint2 g_wqf[1024];
__device__ __align__(16) uint2 g_wkf[1024];
__device__ __align__(16) uint2 g_wvf[1024];
__device__ __align__(16) uint2 g_wof[1024];
__device__ __align__(16) uint2 g_f1f[1024];
__device__ __align__(16) uint2 g_f2f[1024];
__device__ __align__(16) uint2 g_w1f[9 * 512];  // conv 3x3: per tap, kt<4, nt<4
__device__ __align__(16) uint2 g_w2f[512];      // 1x1 32->64: kt<2, nt<8

// ============================================================
// mma helpers
// ============================================================
__device__ __forceinline__ void mma_bf16(float acc[4], uint32_t a0, uint32_t a1,
                                         uint32_t a2, uint32_t a3,
                                         uint32_t b0, uint32_t b1) {
    asm volatile(
        "mma.sync.aligned.m16n8k16.row.col.f32.bf16.bf16.f32 "
        "{%0,%1,%2,%3},{%4,%5,%6,%7},{%8,%9},{%0,%1,%2,%3};"
        : "+f"(acc[0]), "+f"(acc[1]), "+f"(acc[2]), "+f"(acc[3])
        : "r"(a0), "r"(a1), "r"(a2), "r"(a3), "r"(b0), "r"(b1));
}

__device__ __forceinline__ uint32_t pk(float x, float y) {
    __nv_bfloat162 h = __floats2bfloat162_rn(x, y);
    return *(uint32_t*)&h;
}

// C[16 x 64] += A(smem rows, pitch BP) * B(fragment-packed gmem)
__device__ __forceinline__ void gemm8_g(const __nv_bfloat16* __restrict__ A,
                                        const uint2* __restrict__ Bf,
                                        int lane, float acc[8][4]) {
    int g = lane >> 2, tg = lane & 3;
    const __nv_bfloat16* ar = A + g * BP + 2 * tg;
    #pragma unroll
    for (int kt = 0; kt < 4; kt++) {
        uint32_t a0 = *(const uint32_t*)(ar + 16 * kt);
        uint32_t a1 = *(const uint32_t*)(ar + 8 * BP + 16 * kt);
        uint32_t a2 = *(const uint32_t*)(ar + 16 * kt + 8);
        uint32_t a3 = *(const uint32_t*)(ar + 8 * BP + 16 * kt + 8);
        #pragma unroll
        for (int nt = 0; nt < 8; nt++) {
            uint2 b = __ldg(&Bf[(kt * 8 + nt) * 32 + lane]);
            mma_bf16(acc[nt], a0, a1, a2, a3, b.x, b.y);
        }
    }
}

// chained, B from smem (pitch BP)
__device__ __forceinline__ void chain8(const float ca[8][4],
                                       const __nv_bfloat16* __restrict__ B,
                                       int lane, float acc[8][4]) {
    int g = lane >> 2, tg = lane & 3;
    #pragma unroll
    for (int kt = 0; kt < 4; kt++) {
        uint32_t a0 = pk(ca[2 * kt][0], ca[2 * kt][1]);
        uint32_t a1 = pk(ca[2 * kt][2], ca[2 * kt][3]);
        uint32_t a2 = pk(ca[2 * kt + 1][0], ca[2 * kt + 1][1]);
        uint32_t a3 = pk(ca[2 * kt + 1][2], ca[2 * kt + 1][3]);
        #pragma unroll
        for (int nt = 0; nt < 8; nt++) {
            const __nv_bfloat16* br = B + (8 * nt + g) * BP + 2 * tg + 16 * kt;
            mma_bf16(acc[nt], a0, a1, a2, a3,
                     *(const uint32_t*)br, *(const uint32_t*)(br + 8));
        }
    }
}

// chained, B fragment-packed gmem
__device__ __forceinline__ void chain8_g(const float ca[8][4],
                                         const uint2* __restrict__ Bf,
                                         int lane, float acc[8][4]) {
    #pragma unroll
    for (int kt = 0; kt < 4; kt++) {
        uint32_t a0 = pk(ca[2 * kt][0], ca[2 * kt][1]);
        uint32_t a1 = pk(ca[2 * kt][2], ca[2 * kt][3]);
        uint32_t a2 = pk(ca[2 * kt + 1][0], ca[2 * kt + 1][1]);
        uint32_t a3 = pk(ca[2 * kt + 1][2], ca[2 * kt + 1][3]);
        #pragma unroll
        for (int nt = 0; nt < 8; nt++) {
            uint2 b = __ldg(&Bf[(kt * 8 + nt) * 32 + lane]);
            mma_bf16(acc[nt], a0, a1, a2, a3, b.x, b.y);
        }
    }
}

__device__ __forceinline__ void bias8(float acc[8][4], const float* __restrict__ b, int lane) {
    int tg = lane & 3;
    #pragma unroll
    for (int nt = 0; nt < 8; nt++) {
        float b0 = __ldg(b + 8 * nt + 2 * tg);
        float b1 = __ldg(b + 8 * nt + 2 * tg + 1);
        acc[nt][0] = b0; acc[nt][1] = b1; acc[nt][2] = b0; acc[nt][3] = b1;
    }
}

__device__ __forceinline__ void zero8(float acc[8][4]) {
    #pragma unroll
    for (int nt = 0; nt < 8; nt++)
        #pragma unroll
        for (int i = 0; i < 4; i++) acc[nt][i] = 0.f;
}

__device__ __forceinline__ void store8(__nv_bfloat16* __restrict__ D,
                                       const float acc[8][4], int lane) {
    int g = lane >> 2, tg = lane & 3;
    #pragma unroll
    for (int nt = 0; nt < 8; nt++) {
        int col = 8 * nt + 2 * tg;
        *(uint32_t*)(D + g * BP + col) = pk(acc[nt][0], acc[nt][1]);
        *(uint32_t*)(D + (g + 8) * BP + col) = pk(acc[nt][2], acc[nt][3]);
    }
}

// ============================================================
// K0: pack weights into mma-fragment order (bf16 pairs)
// ============================================================
__global__ void k_prep(const float* __restrict__ qk_w, const float* __restrict__ v_w,
                       const float* __restrict__ out_w, const float* __restrict__ fc1_w,
                       const float* __restrict__ fc2_w, const float* __restrict__ ms1_w,
                       const float* __restrict__ ms2_w) {
    int n = blockDim.x * gridDim.x;
    int t0 = blockIdx.x * blockDim.x + threadIdx.x;
    // 64x64 matrices (kt<4, nt<8)
    for (int idx = t0; idx < 1024; idx += n) {
        int kt = idx >> 8, r = idx & 255;
        int nt = r >> 5, lane = r & 31;
        int g = lane >> 2, tg = lane & 3;
        int row = 8 * nt + g, col = 2 * tg + 16 * kt;
        #define PACK64(W) make_uint2(pk((W)[row * 64 + col], (W)[row * 64 + col + 1]), \
                                     pk((W)[row * 64 + col + 8], (W)[row * 64 + col + 9]))
        g_wqf[idx] = PACK64(qk_w);
        g_wkf[idx] = PACK64(qk_w + 4096);
        g_wvf[idx] = PACK64(v_w);
        g_wof[idx] = PACK64(out_w);
        g_f1f[idx] = PACK64(fc1_w);
        g_f2f[idx] = PACK64(fc2_w);
        #undef PACK64
    }
    // conv 3x3: ms1_w [32 o][64 i][9 tap]; frag per tap: kt<4, nt<4
    for (int idx = t0; idx < 9 * 512; idx += n) {
        int tap = idx >> 9, r = idx & 511;
        int kt = r >> 7, r2 = r & 127;
        int nt = r2 >> 5, lane = r2 & 31;
        int g = lane >> 2, tg = lane & 3;
        int row = 8 * nt + g, col = 2 * tg + 16 * kt;
        uint2 u;
        u.x = pk(ms1_w[(row * 64 + col) * 9 + tap],     ms1_w[(row * 64 + col + 1) * 9 + tap]);
        u.y = pk(ms1_w[(row * 64 + col + 8) * 9 + tap], ms1_w[(row * 64 + col + 9) * 9 + tap]);
        g_w1f[idx] = u;
    }
    // 1x1: ms2_w [64 o][32 i]; kt<2, nt<8
    for (int idx = t0; idx < 512; idx += n) {
        int kt = idx >> 8, r = idx & 255;
        int nt = r >> 5, lane = r & 31;
        int g = lane >> 2, tg = lane & 3;
        int row = 8 * nt + g, col = 2 * tg + 16 * kt;
        uint2 u;
        u.x = pk(ms2_w[row * 32 + col],     ms2_w[row * 32 + col + 1]);
        u.y = pk(ms2_w[row * 32 + col + 8], ms2_w[row * 32 + col + 9]);
        g_w2f[idx] = u;
    }
}

// ============================================================
// K1: global average pool per (b,c)
// ============================================================
__global__ void k_gap(const float* __restrict__ x) {
    int bc = blockIdx.x;
    const float4* p = (const float4*)(x + (size_t)bc * PIX);
    float s = 0.f;
    for (int i = threadIdx.x; i < PIX / 4; i += 256) {
        float4 v = p[i];
        s += v.x + v.y + v.z + v.w;
    }
    __shared__ float red[256];
    red[threadIdx.x] = s;
    __syncthreads();
    for (int st = 128; st > 0; st >>= 1) {
        if (threadIdx.x < st) red[threadIdx.x] += red[threadIdx.x + st];
        __syncthreads();
    }
    if (threadIdx.x == 0) g_gap[bc] = red[0] * (1.f / PIX);
}

// ============================================================
// K2: SE gate
// ============================================================
__global__ void k_gate(const float* __restrict__ se1_w, const float* __restrict__ se1_b,
                       const float* __restrict__ se2_w, const float* __restrict__ se2_b) {
    __shared__ float se[NB][4];
    int tid = threadIdx.x;
    if (tid < 32) {
        int b = tid >> 2, j = tid & 3;
        float s = se1_b[j];
        for (int c = 0; c < NC; c++) s += g_gap[b * NC + c] * se1_w[j * NC + c];
        se[b][j] = fmaxf(s, 0.f);
    }
    __syncthreads();
    int b = tid >> 6, o = tid & 63;
    float s = se2_b[o];
    #pragma unroll
    for (int j = 0; j < 4; j++) s += se[b][j] * se2_w[o * 4 + j];
    g_gate[tid] = 1.f / (1.f + __expf(-s));
}

// ============================================================
// K3: window attention, 4 windows/CTA, weights from gmem frags
// ============================================================
__global__ void __launch_bounds__(256, 2) k_attn(
        const float* __restrict__ x,
        const float* __restrict__ qk_b, const float* __restrict__ v_b,
        const float* __restrict__ out_b) {
    extern __shared__ __nv_bfloat16 sb[];
    __nv_bfloat16* xs = sb;                 // [256 tok][BP]
    __nv_bfloat16* ks = sb + 256 * BP;      // [256 tok][BP]
    __nv_bfloat16* vT = sb + 2 * 256 * BP;  // per window [64 ch][BP tok]

    int tid = threadIdx.x, lane = tid & 31, wid = tid >> 5;
    int g = lane >> 2, tg = lane & 3;
    int blk = blockIdx.x;
    int b = blk >> 8, rem = blk & 255;
    int nh = rem >> 3, grp = rem & 7;
    int h0 = nh * 8, gx0 = grp * 32;
    const float* xb = x + (size_t)b * NC * PIX;

    // load 4 windows of tokens (32-wide strip, coalesced)
    for (int idx = tid; idx < 16384; idx += 256) {
        int c = idx >> 8, p = idx & 255;
        int ty = p >> 5, r5 = p & 31;
        int w4l = r5 >> 3, tx = r5 & 7;
        int tok = w4l * 64 + ty * 8 + tx;
        xs[tok * BP + c] = __float2bfloat16(xb[(size_t)c * PIX + (h0 + ty) * HW + gx0 + r5]);
    }
    __syncthreads();

    int w4 = wid >> 1, half = wid & 1;
    int Rb = w4 * 64 + half * 32;
    __nv_bfloat16* vw = vT + w4 * 64 * BP;

    // K & V projections -> smem
    #pragma unroll
    for (int mt = 0; mt < 2; mt++) {
        int R = Rb + 16 * mt;
        float acc[8][4];
        bias8(acc, qk_b + 64, lane);
        gemm8_g(xs + R * BP, g_wkf, lane, acc);
        store8(ks + R * BP, acc, lane);

        bias8(acc, v_b, lane);
        gemm8_g(xs + R * BP, g_wvf, lane, acc);
        int tI = (R - w4 * 64) + g;
        #pragma unroll
        for (int nt = 0; nt < 8; nt++) {
            int ch = 8 * nt + 2 * tg;
            vw[ch * BP + tI]           = __float2bfloat16(acc[nt][0]);
            vw[(ch + 1) * BP + tI]     = __float2bfloat16(acc[nt][1]);
            vw[ch * BP + tI + 8]       = __float2bfloat16(acc[nt][2]);
            vw[(ch + 1) * BP + tI + 8] = __float2bfloat16(acc[nt][3]);
        }
    }
    __syncthreads();

    #pragma unroll
    for (int mt = 0; mt < 2; mt++) {
        int R = Rb + 16 * mt;
        float qac[8][4];
        bias8(qac, qk_b, lane);
        gemm8_g(xs + R * BP, g_wqf, lane, qac);

        float sac[8][4];
        zero8(sac);
        chain8(qac, ks + w4 * 64 * BP, lane, sac);   // scores

        float mx0 = -1e30f, mx1 = -1e30f;
        #pragma unroll
        for (int nt = 0; nt < 8; nt++) {
            mx0 = fmaxf(mx0, fmaxf(sac[nt][0], sac[nt][1]));
            mx1 = fmaxf(mx1, fmaxf(sac[nt][2], sac[nt][3]));
        }
        mx0 = fmaxf(mx0, __shfl_xor_sync(0xffffffffu, mx0, 1));
        mx0 = fmaxf(mx0, __shfl_xor_sync(0xffffffffu, mx0, 2));
        mx1 = fmaxf(mx1, __shfl_xor_sync(0xffffffffu, mx1, 1));
        mx1 = fmaxf(mx1, __shfl_xor_sync(0xffffffffu, mx1, 2));
        float s0 = 0.f, s1 = 0.f;
        #pragma unroll
        for (int nt = 0; nt < 8; nt++) {
            sac[nt][0] = __expf(0.125f * (sac[nt][0] - mx0)); s0 += sac[nt][0];
            sac[nt][1] = __expf(0.125f * (sac[nt][1] - mx0)); s0 += sac[nt][1];
            sac[nt][2] = __expf(0.125f * (sac[nt][2] - mx1)); s1 += sac[nt][2];
            sac[nt][3] = __expf(0.125f * (sac[nt][3] - mx1)); s1 += sac[nt][3];
        }
        s0 += __shfl_xor_sync(0xffffffffu, s0, 1);
        s0 += __shfl_xor_sync(0xffffffffu, s0, 2);
        s1 += __shfl_xor_sync(0xffffffffu, s1, 1);
        s1 += __shfl_xor_sync(0xffffffffu, s1, 2);
        float i0 = 1.f / s0, i1 = 1.f / s1;
        #pragma unroll
        for (int nt = 0; nt < 8; nt++) {
            sac[nt][0] *= i0; sac[nt][1] *= i0;
            sac[nt][2] *= i1; sac[nt][3] *= i1;
        }

        float oac[8][4];
        zero8(oac);
        chain8(sac, vw, lane, oac);                  // P @ V

        float uac[8][4];
        bias8(uac, out_b, lane);
        chain8_g(oac, g_wof, lane, uac);             // out proj

        int t0i = (R - w4 * 64) + g, t1i = t0i + 8;
        size_t p0 = ((size_t)(b * HW + h0 + (t0i >> 3)) * HW + gx0 + w4 * 8 + (t0i & 7)) * (size_t)NC;
        size_t p1 = ((size_t)(b * HW + h0 + (t1i >> 3)) * HW + gx0 + w4 * 8 + (t1i & 7)) * (size_t)NC;
        #pragma unroll
        for (int nt = 0; nt < 8; nt++) {
            int ch = 8 * nt + 2 * tg;
            float ga0 = __ldg(&g_gate[b * NC + ch]);
            float ga1 = __ldg(&g_gate[b * NC + ch + 1]);
            *(float2*)(g_A + p0 + ch) = make_float2(uac[nt][0] * ga0, uac[nt][1] * ga1);
            *(float2*)(g_A + p1 + ch) = make_float2(uac[nt][2] * ga0, uac[nt][3] * ga1);
        }
    }
}

// ============================================================
// K4 (fused tail): 3x3 conv (tensor implicit GEMM) + relu +
// 1x1 chain + x + g_A -> x1 (smem) -> LN -> fc1+GELU -> fc2
// + residual -> out (NCHW). One 16x16 tile / CTA.
// ============================================================
__device__ __forceinline__ float gelu_f(float v) {
    float u = 0.7978845608028654f * (v + 0.044715f * v * v * v);
    return v / (1.f + __expf(-2.f * u));
}

__global__ void __launch_bounds__(256, 2) k_tail(
        const float* __restrict__ x,
        const float* __restrict__ ms1_b, const float* __restrict__ ms2_b,
        const float* __restrict__ ln_g, const float* __restrict__ ln_b,
        const float* __restrict__ fc1_b, const float* __restrict__ fc2_b,
        float* __restrict__ out) {
    extern __shared__ char smc[];
    __nv_bfloat16* halo  = (__nv_bfloat16*)smc;           // [324][BP] = 46656B
    float*         stage = (float*)smc;                   // [256][FP] = 66560B (aliases halo)
    __nv_bfloat16* tn    = (__nv_bfloat16*)(smc + 66560); // [256][BP] = 36864B

    int tid = threadIdx.x, lane = tid & 31, wid = tid >> 5;
    int g = lane >> 2, tg = lane & 3;
    int b = blockIdx.z;
    int gy0 = blockIdx.y << 4, gx0 = blockIdx.x << 4;

    // halo load: [hy*18+hx][ch]
    for (int idx = tid; idx < 20736; idx += 256) {
        int c = idx / 324, r = idx - c * 324;
        int hy = r / 18, hx = r - hy * 18;
        int gy = gy0 + hy - 1, gx = gx0 + hx - 1;
        float v = 0.f;
        if (gy >= 0 && gy < HW && gx >= 0 && gx < HW)
            v = x[((size_t)(b * NC + c)) * PIX + (size_t)gy * HW + gx];
        halo[r * BP + c] = __float2bfloat16(v);
    }
    __syncthreads();

    // conv: warp handles tile rows py0, py0+1
    int py0 = wid * 2;
    float cac[2][4][4];
    #pragma unroll
    for (int row = 0; row < 2; row++)
        #pragma unroll
        for (int nt = 0; nt < 4; nt++)
            #pragma unroll
            for (int i = 0; i < 4; i++) cac[row][nt][i] = 0.f;

    #pragma unroll
    for (int tap = 0; tap < 9; tap++) {
        int ky = tap / 3, kx = tap - ky * 3;
        #pragma unroll
        for (int kt = 0; kt < 4; kt++) {
            uint2 bf[4];
            #pragma unroll
            for (int nt = 0; nt < 4; nt++)
                bf[nt] = __ldg(&g_w1f[tap * 512 + (kt * 4 + nt) * 32 + lane]);
            #pragma unroll
            for (int row = 0; row < 2; row++) {
                const __nv_bfloat16* ar =
                    halo + ((py0 + row + ky) * 18 + kx + g) * BP + 2 * tg + 16 * kt;
                uint32_t a0 = *(const uint32_t*)ar;
                uint32_t a1 = *(const uint32_t*)(ar + 8 * BP);
                uint32_t a2 = *(const uint32_t*)(ar + 8);
                uint32_t a3 = *(const uint32_t*)(ar + 8 * BP + 8);
                #pragma unroll
                for (int nt = 0; nt < 4; nt++)
                    mma_bf16(cac[row][nt], a0, a1, a2, a3, bf[nt].x, bf[nt].y);
            }
        }
    }
    // relu + bias
    #pragma unroll
    for (int row = 0; row < 2; row++)
        #pragma unroll
        for (int nt = 0; nt < 4; nt++) {
            int ch = 8 * nt + 2 * tg;
            float bb0 = __ldg(&ms1_b[ch]), bb1 = __ldg(&ms1_b[ch + 1]);
            cac[row][nt][0] = fmaxf(cac[row][nt][0] + bb0, 0.f);
            cac[row][nt][1] = fmaxf(cac[row][nt][1] + bb1, 0.f);
            cac[row][nt][2] = fmaxf(cac[row][nt][2] + bb0, 0.f);
            cac[row][nt][3] = fmaxf(cac[row][nt][3] + bb1, 0.f);
        }
    // 1x1 32->64 register-chained
    float dac[2][8][4];
    #pragma unroll
    for (int row = 0; row < 2; row++) bias8(dac[row], ms2_b, lane);
    #pragma unroll
    for (int row = 0; row < 2; row++) {
        #pragma unroll
        for (int kt = 0; kt < 2; kt++) {
            uint32_t a0 = pk(cac[row][2 * kt][0], cac[row][2 * kt][1]);
            uint32_t a1 = pk(cac[row][2 * kt][2], cac[row][2 * kt][3]);
            uint32_t a2 = pk(cac[row][2 * kt + 1][0], cac[row][2 * kt + 1][1]);
            uint32_t a3 = pk(cac[row][2 * kt + 1][2], cac[row][2 * kt + 1][3]);
            #pragma unroll
            for (int nt = 0; nt < 8; nt++) {
                uint2 bfr = __ldg(&g_w2f[(kt * 8 + nt) * 32 + lane]);
                mma_bf16(dac[row][nt], a0, a1, a2, a3, bfr.x, bfr.y);
            }
        }
    }
    __syncthreads();   // all halo reads done; stage may overwrite
    #pragma unroll
    for (int row = 0; row < 2; row++) {
        int p0 = (py0 + row) * 16 + g, p1 = p0 + 8;
        #pragma unroll
        for (int nt = 0; nt < 8; nt++) {
            int ch = 8 * nt + 2 * tg;
            stage[p0 * FP + ch]     = dac[row][nt][0];
            stage[p0 * FP + ch + 1] = dac[row][nt][1];
            stage[p1 * FP + ch]     = dac[row][nt][2];
            stage[p1 * FP + ch + 1] = dac[row][nt][3];
        }
    }
    __syncthreads();
    {   // + x residual (fp32, per-channel coalesced)
        int p = tid, py = p >> 4, px = p & 15;
        const float* xp = x + (size_t)b * NC * PIX + (size_t)(gy0 + py) * HW + gx0 + px;
        #pragma unroll 8
        for (int c = 0; c < NC; c++) stage[p * FP + c] += xp[(size_t)c * PIX];
    }
    __syncthreads();
    // + attention residual (g_A NHWC, coalesced)
    for (int idx = tid; idx < 16384; idx += 256) {
        int p = idx >> 6, c = idx & 63;
        int gy = gy0 + (p >> 4), gx = gx0 + (p & 15);
        size_t gi = ((size_t)(b * HW + gy) * HW + gx) * (size_t)NC + c;
        stage[p * FP + c] += g_A[gi];
    }
    __syncthreads();
    {   // LN per pixel -> tn (bf16)
        int p = tid;
        float mu = 0.f;
        #pragma unroll 8
        for (int c = 0; c < NC; c++) mu += stage[p * FP + c];
        mu *= (1.f / NC);
        float var = 0.f;
        #pragma unroll 8
        for (int c = 0; c < NC; c++) { float d = stage[p * FP + c] - mu; var += d * d; }
        var *= (1.f / NC);
        float rs = rsqrtf(var + 1e-5f);
        #pragma unroll 8
        for (int c = 0; c < NC; c++)
            tn[p * BP + c] = __float2bfloat16(
                (stage[p * FP + c] - mu) * rs * __ldg(&ln_g[c]) + __ldg(&ln_b[c]));
    }
    __syncthreads();

    // FFN: fc1 + GELU + fc2 + residual; write out NCHW
    #pragma unroll
    for (int mt = 0; mt < 2; mt++) {
        int R = wid * 32 + 16 * mt;
        float fac[8][4];
        bias8(fac, fc1_b, lane);
        gemm8_g(tn + R * BP, g_f1f, lane, fac);
        #pragma unroll
        for (int nt = 0; nt < 8; nt++)
            #pragma unroll
            for (int i = 0; i < 4; i++) fac[nt][i] = gelu_f(fac[nt][i]);
        float gac[8][4];
        bias8(gac, fc2_b, lane);
        chain8_g(fac, g_f2f, lane, gac);

        int p0 = R + g, p1 = p0 + 8;
        int py0o = p0 >> 4, px0o = p0 & 15;
        int py1o = p1 >> 4, px1o = p1 & 15;
        #pragma unroll
        for (int nt = 0; nt < 8; nt++) {
            int ch = 8 * nt + 2 * tg;
            size_t o0 = ((size_t)(b * NC + ch)) * PIX;
            size_t o1 = ((size_t)(b * NC + ch + 1)) * PIX;
            out[o0 + (size_t)(gy0 + py0o) * HW + gx0 + px0o] = gac[nt][0] + stage[p0 * FP + ch];
            out[o1 + (size_t)(gy0 + py0o) * HW + gx0 + px0o] = gac[nt][1] + stage[p0 * FP + ch + 1];
            out[o0 + (size_t)(gy0 + py1o) * HW + gx0 + px1o] = gac[nt][2] + stage[p1 * FP + ch];
            out[o1 + (size_t)(gy0 + py1o) * HW + gx0 + px1o] = gac[nt][3] + stage[p1 * FP + ch + 1];
        }
    }
}

// ============================================================
extern "C" void kernel_launch(void* const* d_in, const int* in_sizes, int n_in,
                              void* d_out, int out_size) {
    const float* x     = (const float*)d_in[0];
    const float* qk_w  = (const float*)d_in[1];
    const float* qk_b  = (const float*)d_in[2];
    const float* v_w   = (const float*)d_in[3];
    const float* v_b   = (const float*)d_in[4];
    const float* out_w = (const float*)d_in[5];
    const float* out_b = (const float*)d_in[6];
    const float* ms1_w = (const float*)d_in[7];
    const float* ms1_b = (const float*)d_in[8];
    const float* ms2_w = (const float*)d_in[9];
    const float* ms2_b = (const float*)d_in[10];
    const float* se1_w = (const float*)d_in[11];
    const float* se1_b = (const float*)d_in[12];
    const float* se2_w = (const float*)d_in[13];
    const float* se2_b = (const float*)d_in[14];
    const float* ln_g  = (const float*)d_in[15];
    const float* ln_b  = (const float*)d_in[16];
    const float* fc1_w = (const float*)d_in[17];
    const float* fc1_b = (const float*)d_in[18];
    const float* fc2_w = (const float*)d_in[19];
    const float* fc2_b = (const float*)d_in[20];
    float* out = (float*)d_out;

    const int smem_attn = 3 * 256 * BP * 2;        // 110592
    const int smem_tail = 66560 + 36864;           // 103424
    cudaFuncSetAttribute(k_attn, cudaFuncAttributeMaxDynamicSharedMemorySize, smem_attn);
    cudaFuncSetAttribute(k_tail, cudaFuncAttributeMaxDynamicSharedMemorySize, smem_tail);

    k_prep<<<24, 256>>>(qk_w, v_w, out_w, fc1_w, fc2_w, ms1_w, ms2_w);
    k_gap<<<NB * NC, 256>>>(x);
    k_gate<<<1, 512>>>(se1_w, se1_b, se2_w, se2_b);
    k_attn<<<2048, 256, smem_attn>>>(x, qk_b, v_b, out_b);
    k_tail<<<dim3(16, 16, NB), 256, smem_tail>>>(x, ms1_b, ms2_b, ln_g, ln_b,
                                                 fc1_b, fc2_b, out);
}